// round 1
// baseline (speedup 1.0000x reference)
#include <cuda_runtime.h>
#include <cuda_bf16.h>
#include <math.h>

#define SEQ 2048
#define BATCH 2
#define NHEAD 16
#define DHEAD 64
#define DMODEL 1024
#define ROWS (SEQ*BATCH)          // 4096
#define LN_EPS 1e-5f

// ---------------- scratch (static device globals; no allocation) ----------------
__device__ float g_K[BATCH*NHEAD*SEQ*DHEAD];          // [b][n][i][d]
__device__ float g_V[BATCH*NHEAD*SEQ*DHEAD];
__device__ float g_Q[2*BATCH*NHEAD*SEQ*DHEAD];        // [stream][b][n][i][d]
__device__ float g_AV[2*ROWS*DMODEL];                 // attn_vec, row-major (i*2+b, nd)
__device__ float g_AO[2*ROWS*DMODEL];                 // attn_out pre-LN
__device__ float g_WoT[DMODEL*DMODEL];                // WoT[k=nd][j=h]

// ---------------- Wo transpose ----------------
__global__ void transpose1024(const float* __restrict__ in, float* __restrict__ out) {
    __shared__ float t[32][33];
    int x = blockIdx.x*32 + threadIdx.x;
    int y = blockIdx.y*32 + threadIdx.y;
    #pragma unroll
    for (int i = 0; i < 32; i += 8)
        t[threadIdx.y + i][threadIdx.x] = in[(size_t)(y + i)*DMODEL + x];
    __syncthreads();
    x = blockIdx.y*32 + threadIdx.x;
    y = blockIdx.x*32 + threadIdx.y;
    #pragma unroll
    for (int i = 0; i < 32; i += 8)
        out[(size_t)(y + i)*DMODEL + x] = t[threadIdx.x][threadIdx.y + i];
}

// ---------------- SGEMM: (4096x1024) * (1024x1024) ----------------
// mode 0: dst row-major [row][col]
// mode 1: dst head-layout [b][n][i][d]   (row=i*2+b, col=n*64+d)
// mode 2: mode 1 + bias[col] added (r_w_bias)
__global__ __launch_bounds__(256)
void sgemm(const float* __restrict__ A, const float* __restrict__ B,
           float* __restrict__ dst, const float* __restrict__ bias, int mode) {
    const int Kdim = DMODEL, Ncol = DMODEL;
    __shared__ float Ast[16][128];   // transposed A tile: [k][m]
    __shared__ float Bs[16][128];    // [k][n]
    const int tid = threadIdx.x;
    const int tx = tid & 15, ty = tid >> 4;
    const int br = blockIdx.y, bc = blockIdx.x;

    float acc[8][8];
    #pragma unroll
    for (int m = 0; m < 8; m++)
        #pragma unroll
        for (int n = 0; n < 8; n++) acc[m][n] = 0.f;

    for (int k0 = 0; k0 < Kdim; k0 += 16) {
        // A tile: 128x16 -> 512 float4, 2 per thread, store transposed
        #pragma unroll
        for (int li = 0; li < 2; li++) {
            int f = tid + 256*li;
            int r = f >> 2, c4 = f & 3;
            float4 v = *(const float4*)&A[(size_t)(br*128 + r)*Kdim + k0 + c4*4];
            Ast[c4*4 + 0][r] = v.x; Ast[c4*4 + 1][r] = v.y;
            Ast[c4*4 + 2][r] = v.z; Ast[c4*4 + 3][r] = v.w;
        }
        // B tile: 16x128 -> 512 float4
        #pragma unroll
        for (int li = 0; li < 2; li++) {
            int f = tid + 256*li;
            int r = f >> 5, c4 = f & 31;
            *(float4*)&Bs[r][c4*4] = *(const float4*)&B[(size_t)(k0 + r)*Ncol + bc*128 + c4*4];
        }
        __syncthreads();
        #pragma unroll
        for (int k = 0; k < 16; k++) {
            float a[8], b[8];
            *(float4*)&a[0] = *(const float4*)&Ast[k][ty*8];
            *(float4*)&a[4] = *(const float4*)&Ast[k][ty*8 + 4];
            *(float4*)&b[0] = *(const float4*)&Bs[k][tx*4];
            *(float4*)&b[4] = *(const float4*)&Bs[k][64 + tx*4];
            #pragma unroll
            for (int m = 0; m < 8; m++)
                #pragma unroll
                for (int n = 0; n < 8; n++) acc[m][n] += a[m]*b[n];
        }
        __syncthreads();
    }

    #pragma unroll
    for (int m = 0; m < 8; m++) {
        int row = br*128 + ty*8 + m;
        #pragma unroll
        for (int half = 0; half < 2; half++) {
            int c0 = bc*128 + half*64 + tx*4;
            float4 v;
            v.x = acc[m][half*4 + 0]; v.y = acc[m][half*4 + 1];
            v.z = acc[m][half*4 + 2]; v.w = acc[m][half*4 + 3];
            if (mode == 0) {
                *(float4*)&dst[(size_t)row*Ncol + c0] = v;
            } else {
                if (mode == 2) {
                    float4 bb = *(const float4*)&bias[c0];
                    v.x += bb.x; v.y += bb.y; v.z += bb.z; v.w += bb.w;
                }
                int i = row >> 1, b = row & 1;
                int nh = c0 >> 6, d = c0 & 63;
                *(float4*)&dst[((size_t)(b*NHEAD + nh)*SEQ + i)*DHEAD + d] = v;
            }
        }
    }
}

// ---------------- flash attention (fp32) ----------------
// grid: (SEQ/64, BATCH*NHEAD, 2 streams), block 128
// smem: Qs[64][64], Ks[64][65] (reused for P), Vs[64][65]
__global__ __launch_bounds__(128)
void flash_attn(const float* __restrict__ Qall, const float* __restrict__ K,
                const float* __restrict__ V, float* __restrict__ AV) {
    extern __shared__ float sm[];
    float* Qs = sm;               // 64*64
    float* Ks = sm + 64*64;       // 64*65
    float* Vs = Ks + 64*65;       // 64*65

    const int tid = threadIdx.x;
    const int tx = tid & 15, ty = tid >> 4;
    const int i0 = blockIdx.x * 64;
    const int bn = blockIdx.y;
    const int strm = blockIdx.z;

    const float* q  = Qall + ((size_t)strm*BATCH*NHEAD + bn)*SEQ*DHEAD + (size_t)i0*DHEAD;
    const float* kp = K + (size_t)bn*SEQ*DHEAD;
    const float* vp = V + (size_t)bn*SEQ*DHEAD;

    {   // load Q tile (contiguous)
        const float4* q4 = (const float4*)q;
        float4* Qs4 = (float4*)Qs;
        #pragma unroll
        for (int i = 0; i < 8; i++) Qs4[tid + 128*i] = q4[tid + 128*i];
    }

    float m_i[8], l_i[8], acc[8][4];
    #pragma unroll
    for (int m = 0; m < 8; m++) {
        m_i[m] = -1e30f; l_i[m] = 0.f;
        #pragma unroll
        for (int n = 0; n < 4; n++) acc[m][n] = 0.f;
    }

    const float scale = 0.125f;  // 1/sqrt(64)

    for (int j0 = 0; j0 < SEQ; j0 += 64) {
        __syncthreads();  // prev O-gemm done with Ks(P)/Vs
        const float4* k4 = (const float4*)(kp + (size_t)j0*DHEAD);
        const float4* v4 = (const float4*)(vp + (size_t)j0*DHEAD);
        #pragma unroll
        for (int li = 0; li < 8; li++) {
            int f = tid + 128*li;
            int r = f >> 4, c = (f & 15) << 2;
            float4 kv = k4[f];
            float* d1 = &Ks[r*65 + c];
            d1[0] = kv.x; d1[1] = kv.y; d1[2] = kv.z; d1[3] = kv.w;
            float4 vv = v4[f];
            float* d2 = &Vs[r*65 + c];
            d2[0] = vv.x; d2[1] = vv.y; d2[2] = vv.z; d2[3] = vv.w;
        }
        __syncthreads();

        // S = Q * K^T  (8 rows x 4 cols per thread)
        float s[8][4];
        #pragma unroll
        for (int m = 0; m < 8; m++)
            #pragma unroll
            for (int n = 0; n < 4; n++) s[m][n] = 0.f;
        #pragma unroll 8
        for (int d = 0; d < 64; d++) {
            float a[8], bfr[4];
            #pragma unroll
            for (int m = 0; m < 8; m++) a[m] = Qs[(ty*8 + m)*64 + d];
            #pragma unroll
            for (int n = 0; n < 4; n++) bfr[n] = Ks[(tx*4 + n)*65 + d];
            #pragma unroll
            for (int m = 0; m < 8; m++)
                #pragma unroll
                for (int n = 0; n < 4; n++) s[m][n] += a[m]*bfr[n];
        }

        // online softmax
        float mnew[8], alpha[8], rsum[8];
        #pragma unroll
        for (int m = 0; m < 8; m++) {
            float tmax = -1e30f;
            #pragma unroll
            for (int n = 0; n < 4; n++) { s[m][n] *= scale; tmax = fmaxf(tmax, s[m][n]); }
            #pragma unroll
            for (int off = 1; off < 16; off <<= 1)
                tmax = fmaxf(tmax, __shfl_xor_sync(0xffffffffu, tmax, off));
            mnew[m] = fmaxf(m_i[m], tmax);
            alpha[m] = __expf(m_i[m] - mnew[m]);
            float rs = 0.f;
            #pragma unroll
            for (int n = 0; n < 4; n++) {
                float p = __expf(s[m][n] - mnew[m]);
                s[m][n] = p; rs += p;
            }
            #pragma unroll
            for (int off = 1; off < 16; off <<= 1)
                rs += __shfl_xor_sync(0xffffffffu, rs, off);
            rsum[m] = rs;
        }
        #pragma unroll
        for (int m = 0; m < 8; m++) {
            l_i[m] = l_i[m]*alpha[m] + rsum[m];
            m_i[m] = mnew[m];
            #pragma unroll
            for (int n = 0; n < 4; n++) acc[m][n] *= alpha[m];
        }

        __syncthreads();  // all threads done reading Ks
        #pragma unroll
        for (int m = 0; m < 8; m++)
            #pragma unroll
            for (int n = 0; n < 4; n++)
                Ks[(ty*8 + m)*65 + tx*4 + n] = s[m][n];   // P overwrites K
        __syncthreads();

        // O += P * V
        #pragma unroll 8
        for (int c = 0; c < 64; c++) {
            float p[8], vv[4];
            #pragma unroll
            for (int m = 0; m < 8; m++) p[m] = Ks[(ty*8 + m)*65 + c];
            #pragma unroll
            for (int n = 0; n < 4; n++) vv[n] = Vs[c*65 + tx*4 + n];
            #pragma unroll
            for (int m = 0; m < 8; m++)
                #pragma unroll
                for (int n = 0; n < 4; n++) acc[m][n] += p[m]*vv[n];
        }
    }

    // epilogue -> attn_vec row-major (i*2+b, n*64+d)
    const int b = bn >> 4, nh = bn & 15;
    float* outp = AV + (size_t)strm*ROWS*DMODEL;
    #pragma unroll
    for (int m = 0; m < 8; m++) {
        float inv = 1.f / l_i[m];
        int i = i0 + ty*8 + m;
        float4 o;
        o.x = acc[m][0]*inv; o.y = acc[m][1]*inv;
        o.z = acc[m][2]*inv; o.w = acc[m][3]*inv;
        *(float4*)&outp[(size_t)(i*BATCH + b)*DMODEL + nh*DHEAD + tx*4] = o;
    }
}

// ---------------- residual + layernorm ----------------
// grid (ROWS, 2), block 256; each thread 4 consecutive floats
__global__ __launch_bounds__(256)
void resid_ln(const float* __restrict__ AO, const float* __restrict__ h,
              const float* __restrict__ g, const float* __restrict__ gamma,
              const float* __restrict__ beta, float* __restrict__ out) {
    const int row = blockIdx.x;
    const int strm = blockIdx.y;
    const int tid = threadIdx.x;
    const float* x = (strm == 0) ? h : g;
    const float* ao = AO + (size_t)strm*ROWS*DMODEL + (size_t)row*DMODEL;
    const float* xr = x + (size_t)row*DMODEL;

    float4 a4 = *(const float4*)&ao[tid*4];
    float4 x4 = *(const float4*)&xr[tid*4];
    float y[4] = { a4.x + x4.x, a4.y + x4.y, a4.z + x4.z, a4.w + x4.w };

    float s1 = y[0] + y[1] + y[2] + y[3];
    float s2 = y[0]*y[0] + y[1]*y[1] + y[2]*y[2] + y[3]*y[3];
    #pragma unroll
    for (int off = 16; off > 0; off >>= 1) {
        s1 += __shfl_xor_sync(0xffffffffu, s1, off);
        s2 += __shfl_xor_sync(0xffffffffu, s2, off);
    }
    __shared__ float red[18];
    int warp = tid >> 5, lane = tid & 31;
    if (lane == 0) { red[warp*2] = s1; red[warp*2 + 1] = s2; }
    __syncthreads();
    if (tid == 0) {
        float t1 = 0.f, t2 = 0.f;
        #pragma unroll
        for (int w = 0; w < 8; w++) { t1 += red[w*2]; t2 += red[w*2 + 1]; }
        float mu = t1 * (1.f/DMODEL);
        float var = t2 * (1.f/DMODEL) - mu*mu;
        red[16] = mu;
        red[17] = rsqrtf(var + LN_EPS);
    }
    __syncthreads();
    float mu = red[16], inv = red[17];

    float4 g4 = *(const float4*)&gamma[tid*4];
    float4 b4 = *(const float4*)&beta[tid*4];
    float4 o;
    o.x = g4.x*(y[0] - mu)*inv + b4.x;
    o.y = g4.y*(y[1] - mu)*inv + b4.y;
    o.z = g4.z*(y[2] - mu)*inv + b4.z;
    o.w = g4.w*(y[3] - mu)*inv + b4.w;
    *(float4*)&out[(size_t)strm*ROWS*DMODEL + (size_t)row*DMODEL + tid*4] = o;
}

// ---------------- launch ----------------
extern "C" void kernel_launch(void* const* d_in, const int* in_sizes, int n_in,
                              void* d_out, int out_size) {
    const float* h     = (const float*)d_in[0];
    const float* g     = (const float*)d_in[1];
    const float* Wq    = (const float*)d_in[2];
    const float* Wk    = (const float*)d_in[3];
    const float* Wv    = (const float*)d_in[4];
    const float* Wo    = (const float*)d_in[5];
    const float* rwb   = (const float*)d_in[6];
    const float* gamma = (const float*)d_in[7];
    const float* beta  = (const float*)d_in[8];
    float* out = (float*)d_out;

    float *pK, *pV, *pQ, *pAV, *pAO, *pWoT;
    cudaGetSymbolAddress((void**)&pK,   g_K);
    cudaGetSymbolAddress((void**)&pV,   g_V);
    cudaGetSymbolAddress((void**)&pQ,   g_Q);
    cudaGetSymbolAddress((void**)&pAV,  g_AV);
    cudaGetSymbolAddress((void**)&pAO,  g_AO);
    cudaGetSymbolAddress((void**)&pWoT, g_WoT);

    transpose1024<<<dim3(32, 32), dim3(32, 8)>>>(Wo, pWoT);

    dim3 ggrid(8, 32);
    sgemm<<<ggrid, 256>>>(h, Wk, pK, nullptr, 1);
    sgemm<<<ggrid, 256>>>(h, Wv, pV, nullptr, 1);
    sgemm<<<ggrid, 256>>>(h, Wq, pQ, rwb, 2);
    sgemm<<<ggrid, 256>>>(g, Wq, pQ + (size_t)BATCH*NHEAD*SEQ*DHEAD, rwb, 2);

    int smb = (64*64 + 2*64*65) * (int)sizeof(float);   // 49664 B
    cudaFuncSetAttribute(flash_attn, cudaFuncAttributeMaxDynamicSharedMemorySize, smb);
    flash_attn<<<dim3(SEQ/64, BATCH*NHEAD, 2), 128, smb>>>(pQ, pK, pV, pAV);

    sgemm<<<ggrid, 256>>>(pAV, pWoT, pAO, nullptr, 0);
    sgemm<<<ggrid, 256>>>(pAV + (size_t)ROWS*DMODEL, pWoT, pAO + (size_t)ROWS*DMODEL, nullptr, 0);

    resid_ln<<<dim3(ROWS, 2), 256>>>(pAO, h, g, gamma, beta, out);
}

// round 3
// speedup vs baseline: 1.3088x; 1.3088x over previous
#include <cuda_runtime.h>
#include <cuda_bf16.h>
#include <cstdint>
#include <math.h>

#define SEQ 2048
#define BATCH 2
#define NHEAD 16
#define DHEAD 64
#define DMODEL 1024
#define ROWS (SEQ*BATCH)          // 4096
#define LN_EPS 1e-5f

// ---------------- scratch (static device globals; no allocation) ----------------
__device__ __align__(16) float g_K[BATCH*NHEAD*SEQ*DHEAD];          // [b][n][i][d]
__device__ __align__(16) float g_V[BATCH*NHEAD*SEQ*DHEAD];
__device__ __align__(16) float g_Q[2*BATCH*NHEAD*SEQ*DHEAD];        // [stream][b][n][i][d]
__device__ __align__(16) float g_AV[2*ROWS*DMODEL];                 // attn_vec, row-major
__device__ __align__(16) float g_AO[2*ROWS*DMODEL];                 // attn_out pre-LN
__device__ __align__(16) float g_WqT[DMODEL*DMODEL];                // [n][k]
__device__ __align__(16) float g_WkT[DMODEL*DMODEL];
__device__ __align__(16) float g_WvT[DMODEL*DMODEL];

// ================= PTX helpers (base sm_103 target only; NO tcgen05) =================
__device__ __forceinline__ uint32_t s2u(const void* p) {
    uint32_t a;
    asm("{ .reg .u64 t; cvta.to.shared.u64 t, %1; cvt.u32.u64 %0, t; }" : "=r"(a) : "l"(p));
    return a;
}
#define CP_ASYNC16(dst, src) asm volatile("cp.async.cg.shared.global [%0], [%1], 16;" :: "r"(dst), "l"(src))
#define CP_COMMIT()  asm volatile("cp.async.commit_group;")
#define CP_WAIT1()   asm volatile("cp.async.wait_group 1;" ::: "memory")
#define CP_WAIT0()   asm volatile("cp.async.wait_group 0;" ::: "memory")

__device__ __forceinline__ uint32_t f2tf(float f) {
    uint32_t u;
    asm("cvt.rna.tf32.f32 %0, %1;" : "=r"(u) : "f"(f));
    return u;
}
__device__ __forceinline__ void mma_tf32(float* d, const uint32_t* a, const uint32_t* b) {
    asm volatile("mma.sync.aligned.m16n8k8.row.col.f32.tf32.tf32.f32 "
        "{%0,%1,%2,%3},{%4,%5,%6,%7},{%8,%9},{%0,%1,%2,%3};"
        : "+f"(d[0]), "+f"(d[1]), "+f"(d[2]), "+f"(d[3])
        : "r"(a[0]), "r"(a[1]), "r"(a[2]), "r"(a[3]), "r"(b[0]), "r"(b[1]));
}

// ---------------- transpose: out[n][k] = in[k][n] ----------------
__global__ void transpose1024(const float* __restrict__ in, float* __restrict__ out) {
    __shared__ float t[32][33];
    int x = blockIdx.x*32 + threadIdx.x;
    int y = blockIdx.y*32 + threadIdx.y;
    #pragma unroll
    for (int i = 0; i < 32; i += 8)
        t[threadIdx.y + i][threadIdx.x] = in[(size_t)(y + i)*DMODEL + x];
    __syncthreads();
    x = blockIdx.y*32 + threadIdx.x;
    y = blockIdx.x*32 + threadIdx.y;
    #pragma unroll
    for (int i = 0; i < 32; i += 8)
        out[(size_t)(y + i)*DMODEL + x] = t[threadIdx.x][threadIdx.y + i];
}

// ---------------- tf32 mma.sync GEMM: C[4096x1024] = A[4096x1024] * BT^T ----------------
// BT is [N][K] K-major. CTA 128x128, 8 warps (4 M x 2 N), warp tile 32x64, K-chunk 32.
// mode 0: dst row-major; mode 1: head-layout [b][n][i][d]; mode 2: mode1 + bias[col]
#define GPAD 36
#define GTILE (128*GPAD)                 // floats per buffer
#define GSMEM (4*GTILE*4)                // 73728 bytes: A0,A1,B0,B1

__global__ __launch_bounds__(256)
void mma_gemm(const float* __restrict__ A, const float* __restrict__ BT,
              float* __restrict__ dst, const float* __restrict__ bias, int mode) {
    extern __shared__ float sm[];
    float* Ab[2] = { sm,            sm + GTILE };
    float* Bb[2] = { sm + 2*GTILE,  sm + 3*GTILE };
    const uint32_t sbase = s2u(sm);

    const int tid  = threadIdx.x;
    const int lane = tid & 31, warp = tid >> 5;
    const int wm = warp & 3, wn = warp >> 2;       // 4 warps M x 2 warps N
    const int br = blockIdx.y, bc = blockIdx.x;

    // global src + smem dst slots for cp.async (per thread: 4 x 16B for A, 4 for B)
    const float* srcA[4]; const float* srcB[4]; uint32_t doff[4];
    #pragma unroll
    for (int i = 0; i < 4; i++) {
        int f = tid + 256*i;
        int row = f >> 3, seg = f & 7;
        srcA[i] = A  + (size_t)(br*128 + row)*DMODEL + seg*4;
        srcB[i] = BT + (size_t)(bc*128 + row)*DMODEL + seg*4;
        doff[i] = (uint32_t)(row*GPAD + seg*4) * 4u;   // bytes
    }

    auto load_chunk = [&](int c) {
        int buf = c & 1;
        uint32_t abase = sbase + (uint32_t)(buf*GTILE)*4u;
        uint32_t bbase = sbase + (uint32_t)((2 + buf)*GTILE)*4u;
        int kb = c * 32;
        #pragma unroll
        for (int i = 0; i < 4; i++) {
            CP_ASYNC16(abase + doff[i], (const void*)(srcA[i] + kb));
            CP_ASYNC16(bbase + doff[i], (const void*)(srcB[i] + kb));
        }
        CP_COMMIT();
    };

    float d[2][8][4];
    #pragma unroll
    for (int mt = 0; mt < 2; mt++)
        #pragma unroll
        for (int nt = 0; nt < 8; nt++)
            #pragma unroll
            for (int j = 0; j < 4; j++) d[mt][nt][j] = 0.f;

    load_chunk(0);
    load_chunk(1);

    const int arow = wm*32 + (lane >> 2);      // A fragment row base (mt*16, +8 added later)
    const int brow = wn*64 + (lane >> 2);      // B fragment n-row base (nt*8)
    const int kcol = lane & 3;

    for (int c = 0; c < 32; c++) {
        if (c == 31) { CP_WAIT0(); } else { CP_WAIT1(); }
        __syncthreads();
        const float* As = Ab[c & 1];
        const float* Bs = Bb[c & 1];

        #pragma unroll
        for (int ks = 0; ks < 4; ks++) {
            const int ck = ks*8 + kcol;
            uint32_t afr[2][4], bfr[8][2];
            #pragma unroll
            for (int mt = 0; mt < 2; mt++) {
                const float* p = As + (arow + mt*16)*GPAD + ck;
                afr[mt][0] = f2tf(p[0]);
                afr[mt][1] = f2tf(p[8*GPAD]);
                afr[mt][2] = f2tf(p[4]);
                afr[mt][3] = f2tf(p[8*GPAD + 4]);
            }
            #pragma unroll
            for (int nt = 0; nt < 8; nt++) {
                const float* p = Bs + (brow + nt*8)*GPAD + ck;
                bfr[nt][0] = f2tf(p[0]);
                bfr[nt][1] = f2tf(p[4]);
            }
            #pragma unroll
            for (int mt = 0; mt < 2; mt++)
                #pragma unroll
                for (int nt = 0; nt < 8; nt++)
                    mma_tf32(d[mt][nt], afr[mt], bfr[nt]);
        }
        __syncthreads();
        if (c + 2 < 32) load_chunk(c + 2);
    }

    // epilogue: fragment (rows lane/4, +8; cols 2*(lane%3..)) -> float2 stores
    const int r0 = wm*32 + (lane >> 2);
    const int cb = wn*64 + 2*(lane & 3);
    #pragma unroll
    for (int mt = 0; mt < 2; mt++) {
        #pragma unroll
        for (int rh = 0; rh < 2; rh++) {
            int row_g = br*128 + r0 + mt*16 + rh*8;
            #pragma unroll
            for (int nt = 0; nt < 8; nt++) {
                int col_g = bc*128 + cb + nt*8;
                float2 v = make_float2(d[mt][nt][2*rh], d[mt][nt][2*rh + 1]);
                if (mode == 0) {
                    *(float2*)&dst[(size_t)row_g*DMODEL + col_g] = v;
                } else {
                    if (mode == 2) {
                        v.x += bias[col_g];
                        v.y += bias[col_g + 1];
                    }
                    int i = row_g >> 1, b = row_g & 1;
                    int nh = col_g >> 6, dd = col_g & 63;
                    *(float2*)&g_K[0 /*dummy*/] ; // (no-op removed below)
                    *(float2*)&dst[((size_t)(b*NHEAD + nh)*SEQ + i)*DHEAD + dd] = v;
                }
            }
        }
    }
}

// ---------------- flash attention (fp32) ----------------
__global__ __launch_bounds__(128)
void flash_attn(const float* __restrict__ Qall, const float* __restrict__ K,
                const float* __restrict__ V, float* __restrict__ AV) {
    extern __shared__ float smf[];
    float* Qs = smf;              // 64*64
    float* Ks = smf + 64*64;      // 64*65
    float* Vs = Ks + 64*65;       // 64*65

    const int tid = threadIdx.x;
    const int tx = tid & 15, ty = tid >> 4;
    const int i0 = blockIdx.x * 64;
    const int bn = blockIdx.y;
    const int strm = blockIdx.z;

    const float* q  = Qall + ((size_t)strm*BATCH*NHEAD + bn)*SEQ*DHEAD + (size_t)i0*DHEAD;
    const float* kp = K + (size_t)bn*SEQ*DHEAD;
    const float* vp = V + (size_t)bn*SEQ*DHEAD;

    {
        const float4* q4 = (const float4*)q;
        float4* Qs4 = (float4*)Qs;
        #pragma unroll
        for (int i = 0; i < 8; i++) Qs4[tid + 128*i] = q4[tid + 128*i];
    }

    float m_i[8], l_i[8], acc[8][4];
    #pragma unroll
    for (int m = 0; m < 8; m++) {
        m_i[m] = -1e30f; l_i[m] = 0.f;
        #pragma unroll
        for (int n = 0; n < 4; n++) acc[m][n] = 0.f;
    }

    const float scale = 0.125f;

    for (int j0 = 0; j0 < SEQ; j0 += 64) {
        __syncthreads();
        const float4* k4 = (const float4*)(kp + (size_t)j0*DHEAD);
        const float4* v4 = (const float4*)(vp + (size_t)j0*DHEAD);
        #pragma unroll
        for (int li = 0; li < 8; li++) {
            int f = tid + 128*li;
            int r = f >> 4, c = (f & 15) << 2;
            float4 kv = k4[f];
            float* d1 = &Ks[r*65 + c];
            d1[0] = kv.x; d1[1] = kv.y; d1[2] = kv.z; d1[3] = kv.w;
            float4 vv = v4[f];
            float* d2 = &Vs[r*65 + c];
            d2[0] = vv.x; d2[1] = vv.y; d2[2] = vv.z; d2[3] = vv.w;
        }
        __syncthreads();

        float s[8][4];
        #pragma unroll
        for (int m = 0; m < 8; m++)
            #pragma unroll
            for (int n = 0; n < 4; n++) s[m][n] = 0.f;
        #pragma unroll 8
        for (int dd = 0; dd < 64; dd++) {
            float a[8], bfr[4];
            #pragma unroll
            for (int m = 0; m < 8; m++) a[m] = Qs[(ty*8 + m)*64 + dd];
            #pragma unroll
            for (int n = 0; n < 4; n++) bfr[n] = Ks[(tx*4 + n)*65 + dd];
            #pragma unroll
            for (int m = 0; m < 8; m++)
                #pragma unroll
                for (int n = 0; n < 4; n++) s[m][n] += a[m]*bfr[n];
        }

        float mnew[8], alpha[8], rsum[8];
        #pragma unroll
        for (int m = 0; m < 8; m++) {
            float tmax = -1e30f;
            #pragma unroll
            for (int n = 0; n < 4; n++) { s[m][n] *= scale; tmax = fmaxf(tmax, s[m][n]); }
            #pragma unroll
            for (int off = 1; off < 16; off <<= 1)
                tmax = fmaxf(tmax, __shfl_xor_sync(0xffffffffu, tmax, off));
            mnew[m] = fmaxf(m_i[m], tmax);
            alpha[m] = __expf(m_i[m] - mnew[m]);
            float rs = 0.f;
            #pragma unroll
            for (int n = 0; n < 4; n++) {
                float p = __expf(s[m][n] - mnew[m]);
                s[m][n] = p; rs += p;
            }
            #pragma unroll
            for (int off = 1; off < 16; off <<= 1)
                rs += __shfl_xor_sync(0xffffffffu, rs, off);
            rsum[m] = rs;
        }
        #pragma unroll
        for (int m = 0; m < 8; m++) {
            l_i[m] = l_i[m]*alpha[m] + rsum[m];
            m_i[m] = mnew[m];
            #pragma unroll
            for (int n = 0; n < 4; n++) acc[m][n] *= alpha[m];
        }

        __syncthreads();
        #pragma unroll
        for (int m = 0; m < 8; m++)
            #pragma unroll
            for (int n = 0; n < 4; n++)
                Ks[(ty*8 + m)*65 + tx*4 + n] = s[m][n];
        __syncthreads();

        #pragma unroll 8
        for (int cc = 0; cc < 64; cc++) {
            float p[8], vv[4];
            #pragma unroll
            for (int m = 0; m < 8; m++) p[m] = Ks[(ty*8 + m)*65 + cc];
            #pragma unroll
            for (int n = 0; n < 4; n++) vv[n] = Vs[cc*65 + tx*4 + n];
            #pragma unroll
            for (int m = 0; m < 8; m++)
                #pragma unroll
                for (int n = 0; n < 4; n++) acc[m][n] += p[m]*vv[n];
        }
    }

    const int b = bn >> 4, nh = bn & 15;
    float* outp = AV + (size_t)strm*ROWS*DMODEL;
    #pragma unroll
    for (int m = 0; m < 8; m++) {
        float inv = 1.f / l_i[m];
        int i = i0 + ty*8 + m;
        float4 o;
        o.x = acc[m][0]*inv; o.y = acc[m][1]*inv;
        o.z = acc[m][2]*inv; o.w = acc[m][3]*inv;
        *(float4*)&outp[(size_t)(i*BATCH + b)*DMODEL + nh*DHEAD + tx*4] = o;
    }
}

// ---------------- residual + layernorm ----------------
__global__ __launch_bounds__(256)
void resid_ln(const float* __restrict__ AO, const float* __restrict__ h,
              const float* __restrict__ g, const float* __restrict__ gamma,
              const float* __restrict__ beta, float* __restrict__ out) {
    const int row = blockIdx.x;
    const int strm = blockIdx.y;
    const int tid = threadIdx.x;
    const float* x = (strm == 0) ? h : g;
    const float* ao = AO + (size_t)strm*ROWS*DMODEL + (size_t)row*DMODEL;
    const float* xr = x + (size_t)row*DMODEL;

    float4 a4 = *(const float4*)&ao[tid*4];
    float4 x4 = *(const float4*)&xr[tid*4];
    float y[4] = { a4.x + x4.x, a4.y + x4.y, a4.z + x4.z, a4.w + x4.w };

    float s1 = y[0] + y[1] + y[2] + y[3];
    float s2 = y[0]*y[0] + y[1]*y[1] + y[2]*y[2] + y[3]*y[3];
    #pragma unroll
    for (int off = 16; off > 0; off >>= 1) {
        s1 += __shfl_xor_sync(0xffffffffu, s1, off);
        s2 += __shfl_xor_sync(0xffffffffu, s2, off);
    }
    __shared__ float red[18];
    int warp = tid >> 5, lane = tid & 31;
    if (lane == 0) { red[warp*2] = s1; red[warp*2 + 1] = s2; }
    __syncthreads();
    if (tid == 0) {
        float t1 = 0.f, t2 = 0.f;
        #pragma unroll
        for (int w = 0; w < 8; w++) { t1 += red[w*2]; t2 += red[w*2 + 1]; }
        float mu = t1 * (1.f/DMODEL);
        float var = t2 * (1.f/DMODEL) - mu*mu;
        red[16] = mu;
        red[17] = rsqrtf(var + LN_EPS);
    }
    __syncthreads();
    float mu = red[16], inv = red[17];

    float4 g4 = *(const float4*)&gamma[tid*4];
    float4 b4 = *(const float4*)&beta[tid*4];
    float4 o;
    o.x = g4.x*(y[0] - mu)*inv + b4.x;
    o.y = g4.y*(y[1] - mu)*inv + b4.y;
    o.z = g4.z*(y[2] - mu)*inv + b4.z;
    o.w = g4.w*(y[3] - mu)*inv + b4.w;
    *(float4*)&out[(size_t)strm*ROWS*DMODEL + (size_t)row*DMODEL + tid*4] = o;
}

// ---------------- launch ----------------
extern "C" void kernel_launch(void* const* d_in, const int* in_sizes, int n_in,
                              void* d_out, int out_size) {
    const float* h     = (const float*)d_in[0];
    const float* g     = (const float*)d_in[1];
    const float* Wq    = (const float*)d_in[2];
    const float* Wk    = (const float*)d_in[3];
    const float* Wv    = (const float*)d_in[4];
    const float* Wo    = (const float*)d_in[5];
    const float* rwb   = (const float*)d_in[6];
    const float* gamma = (const float*)d_in[7];
    const float* beta  = (const float*)d_in[8];
    float* out = (float*)d_out;

    float *pK, *pV, *pQ, *pAV, *pAO, *pWqT, *pWkT, *pWvT;
    cudaGetSymbolAddress((void**)&pK,   g_K);
    cudaGetSymbolAddress((void**)&pV,   g_V);
    cudaGetSymbolAddress((void**)&pQ,   g_Q);
    cudaGetSymbolAddress((void**)&pAV,  g_AV);
    cudaGetSymbolAddress((void**)&pAO,  g_AO);
    cudaGetSymbolAddress((void**)&pWqT, g_WqT);
    cudaGetSymbolAddress((void**)&pWkT, g_WkT);
    cudaGetSymbolAddress((void**)&pWvT, g_WvT);

    cudaFuncSetAttribute(mma_gemm, cudaFuncAttributeMaxDynamicSharedMemorySize, GSMEM);

    transpose1024<<<dim3(32, 32), dim3(32, 8)>>>(Wq, pWqT);
    transpose1024<<<dim3(32, 32), dim3(32, 8)>>>(Wk, pWkT);
    transpose1024<<<dim3(32, 32), dim3(32, 8)>>>(Wv, pWvT);

    dim3 ggrid(8, 32);
    mma_gemm<<<ggrid, 256, GSMEM>>>(h, pWkT, pK, nullptr, 1);
    mma_gemm<<<ggrid, 256, GSMEM>>>(h, pWvT, pV, nullptr, 1);
    mma_gemm<<<ggrid, 256, GSMEM>>>(h, pWqT, pQ, rwb, 2);
    mma_gemm<<<ggrid, 256, GSMEM>>>(g, pWqT, pQ + (size_t)BATCH*NHEAD*SEQ*DHEAD, rwb, 2);

    int smb = (64*64 + 2*64*65) * (int)sizeof(float);   // 49664 B
    cudaFuncSetAttribute(flash_attn, cudaFuncAttributeMaxDynamicSharedMemorySize, smb);
    flash_attn<<<dim3(SEQ/64, BATCH*NHEAD, 2), 128, smb>>>(pQ, pK, pV, pAV);

    mma_gemm<<<ggrid, 256, GSMEM>>>(pAV, Wo, pAO, nullptr, 0);
    mma_gemm<<<ggrid, 256, GSMEM>>>(pAV + (size_t)ROWS*DMODEL, Wo, pAO + (size_t)ROWS*DMODEL, nullptr, 0);

    resid_ln<<<dim3(ROWS, 2), 256>>>(pAO, h, g, gamma, beta, out);
}

// round 4
// speedup vs baseline: 2.5580x; 1.9545x over previous
#include <cuda_runtime.h>
#include <cuda_bf16.h>
#include <cstdint>
#include <math.h>

#define SEQ 2048
#define BATCH 2
#define NHEAD 16
#define DHEAD 64
#define DMODEL 1024
#define ROWS (SEQ*BATCH)          // 4096
#define LN_EPS 1e-5f

// ---------------- scratch (static device globals; no allocation) ----------------
__device__ __align__(16) float g_K[BATCH*NHEAD*SEQ*DHEAD];          // [b][n][i][d]
__device__ __align__(16) float g_V[BATCH*NHEAD*SEQ*DHEAD];
__device__ __align__(16) float g_Q[2*BATCH*NHEAD*SEQ*DHEAD];        // [stream][b][n][i][d]
__device__ __align__(16) float g_AV[2*ROWS*DMODEL];                 // attn_vec, row-major
__device__ __align__(16) float g_AO[2*ROWS*DMODEL];                 // attn_out pre-LN
__device__ __align__(16) float g_WqT[DMODEL*DMODEL];                // [n][k]
__device__ __align__(16) float g_WkT[DMODEL*DMODEL];
__device__ __align__(16) float g_WvT[DMODEL*DMODEL];

// ================= PTX helpers (base sm_103 target only) =================
__device__ __forceinline__ uint32_t s2u(const void* p) {
    uint32_t a;
    asm("{ .reg .u64 t; cvta.to.shared.u64 t, %1; cvt.u32.u64 %0, t; }" : "=r"(a) : "l"(p));
    return a;
}
#define CP_ASYNC16(dst, src) asm volatile("cp.async.cg.shared.global [%0], [%1], 16;" :: "r"(dst), "l"(src))
#define CP_COMMIT()  asm volatile("cp.async.commit_group;")
#define CP_WAIT1()   asm volatile("cp.async.wait_group 1;" ::: "memory")
#define CP_WAIT0()   asm volatile("cp.async.wait_group 0;" ::: "memory")

__device__ __forceinline__ uint32_t f2tf(float f) {
    uint32_t u;
    asm("cvt.rna.tf32.f32 %0, %1;" : "=r"(u) : "f"(f));
    return u;
}
__device__ __forceinline__ void mma_tf32(float* d, const uint32_t* a, const uint32_t* b) {
    asm volatile("mma.sync.aligned.m16n8k8.row.col.f32.tf32.tf32.f32 "
        "{%0,%1,%2,%3},{%4,%5,%6,%7},{%8,%9},{%0,%1,%2,%3};"
        : "+f"(d[0]), "+f"(d[1]), "+f"(d[2]), "+f"(d[3])
        : "r"(a[0]), "r"(a[1]), "r"(a[2]), "r"(a[3]), "r"(b[0]), "r"(b[1]));
}

// ---------------- transpose: out[n][k] = in[k][n] ----------------
__global__ void transpose1024(const float* __restrict__ in, float* __restrict__ out) {
    __shared__ float t[32][33];
    int x = blockIdx.x*32 + threadIdx.x;
    int y = blockIdx.y*32 + threadIdx.y;
    #pragma unroll
    for (int i = 0; i < 32; i += 8)
        t[threadIdx.y + i][threadIdx.x] = in[(size_t)(y + i)*DMODEL + x];
    __syncthreads();
    x = blockIdx.y*32 + threadIdx.x;
    y = blockIdx.x*32 + threadIdx.y;
    #pragma unroll
    for (int i = 0; i < 32; i += 8)
        out[(size_t)(y + i)*DMODEL + x] = t[threadIdx.x][threadIdx.y + i];
}

// ---------------- tf32 mma.sync GEMM (unchanged from R3) ----------------
#define GPAD 36
#define GTILE (128*GPAD)
#define GSMEM (4*GTILE*4)

__global__ __launch_bounds__(256)
void mma_gemm(const float* __restrict__ A, const float* __restrict__ BT,
              float* __restrict__ dst, const float* __restrict__ bias, int mode) {
    extern __shared__ float sm[];
    float* Ab[2] = { sm,            sm + GTILE };
    float* Bb[2] = { sm + 2*GTILE,  sm + 3*GTILE };
    const uint32_t sbase = s2u(sm);

    const int tid  = threadIdx.x;
    const int lane = tid & 31, warp = tid >> 5;
    const int wm = warp & 3, wn = warp >> 2;
    const int br = blockIdx.y, bc = blockIdx.x;

    const float* srcA[4]; const float* srcB[4]; uint32_t doff[4];
    #pragma unroll
    for (int i = 0; i < 4; i++) {
        int f = tid + 256*i;
        int row = f >> 3, seg = f & 7;
        srcA[i] = A  + (size_t)(br*128 + row)*DMODEL + seg*4;
        srcB[i] = BT + (size_t)(bc*128 + row)*DMODEL + seg*4;
        doff[i] = (uint32_t)(row*GPAD + seg*4) * 4u;
    }

    auto load_chunk = [&](int c) {
        int buf = c & 1;
        uint32_t abase = sbase + (uint32_t)(buf*GTILE)*4u;
        uint32_t bbase = sbase + (uint32_t)((2 + buf)*GTILE)*4u;
        int kb = c * 32;
        #pragma unroll
        for (int i = 0; i < 4; i++) {
            CP_ASYNC16(abase + doff[i], (const void*)(srcA[i] + kb));
            CP_ASYNC16(bbase + doff[i], (const void*)(srcB[i] + kb));
        }
        CP_COMMIT();
    };

    float d[2][8][4];
    #pragma unroll
    for (int mt = 0; mt < 2; mt++)
        #pragma unroll
        for (int nt = 0; nt < 8; nt++)
            #pragma unroll
            for (int j = 0; j < 4; j++) d[mt][nt][j] = 0.f;

    load_chunk(0);
    load_chunk(1);

    const int arow = wm*32 + (lane >> 2);
    const int brow = wn*64 + (lane >> 2);
    const int kcol = lane & 3;

    for (int c = 0; c < 32; c++) {
        if (c == 31) { CP_WAIT0(); } else { CP_WAIT1(); }
        __syncthreads();
        const float* As = Ab[c & 1];
        const float* Bs = Bb[c & 1];

        #pragma unroll
        for (int ks = 0; ks < 4; ks++) {
            const int ck = ks*8 + kcol;
            uint32_t afr[2][4], bfr[8][2];
            #pragma unroll
            for (int mt = 0; mt < 2; mt++) {
                const float* p = As + (arow + mt*16)*GPAD + ck;
                afr[mt][0] = f2tf(p[0]);
                afr[mt][1] = f2tf(p[8*GPAD]);
                afr[mt][2] = f2tf(p[4]);
                afr[mt][3] = f2tf(p[8*GPAD + 4]);
            }
            #pragma unroll
            for (int nt = 0; nt < 8; nt++) {
                const float* p = Bs + (brow + nt*8)*GPAD + ck;
                bfr[nt][0] = f2tf(p[0]);
                bfr[nt][1] = f2tf(p[4]);
            }
            #pragma unroll
            for (int mt = 0; mt < 2; mt++)
                #pragma unroll
                for (int nt = 0; nt < 8; nt++)
                    mma_tf32(d[mt][nt], afr[mt], bfr[nt]);
        }
        __syncthreads();
        if (c + 2 < 32) load_chunk(c + 2);
    }

    const int r0 = wm*32 + (lane >> 2);
    const int cb = wn*64 + 2*(lane & 3);
    #pragma unroll
    for (int mt = 0; mt < 2; mt++) {
        #pragma unroll
        for (int rh = 0; rh < 2; rh++) {
            int row_g = br*128 + r0 + mt*16 + rh*8;
            #pragma unroll
            for (int nt = 0; nt < 8; nt++) {
                int col_g = bc*128 + cb + nt*8;
                float2 v = make_float2(d[mt][nt][2*rh], d[mt][nt][2*rh + 1]);
                if (mode == 0) {
                    *(float2*)&dst[(size_t)row_g*DMODEL + col_g] = v;
                } else {
                    if (mode == 2) {
                        v.x += bias[col_g];
                        v.y += bias[col_g + 1];
                    }
                    int i = row_g >> 1, b = row_g & 1;
                    int nh = col_g >> 6, dd = col_g & 63;
                    *(float2*)&dst[((size_t)(b*NHEAD + nh)*SEQ + i)*DHEAD + dd] = v;
                }
            }
        }
    }
}

// ---------------- flash attention on mma.sync tf32 ----------------
// grid (SEQ/128, BATCH*NHEAD, 2), block 256 (8 warps x 16 rows)
// smem: Ks[64][68] (tf32 K, [j][d]), Vt[64][68] (tf32 V^T, [d][j]),
//       Ps[128][68] (tf32 P per-warp-private rows; also Q staging)
#define FPAD 68
#define FSMEM ((64*FPAD + 64*FPAD + 128*FPAD)*4)   // 69632 B

__global__ __launch_bounds__(256)
void flash_mma(const float* __restrict__ Qall, const float* __restrict__ K,
               const float* __restrict__ V, float* __restrict__ AV) {
    extern __shared__ uint32_t fsm[];
    uint32_t* Ks = fsm;                  // 64*FPAD
    uint32_t* Vt = fsm + 64*FPAD;        // 64*FPAD
    uint32_t* Ps = fsm + 128*FPAD;       // 128*FPAD
    float* Qstage = (float*)Ps;

    const int tid = threadIdx.x, lane = tid & 31, warp = tid >> 5;
    const int r = lane >> 2, qd = lane & 3;
    const int wr = warp*16;
    const int i0 = blockIdx.x*128;
    const int bn = blockIdx.y, strm = blockIdx.z;

    const float* q  = Qall + ((size_t)strm*BATCH*NHEAD + bn)*SEQ*DHEAD + (size_t)i0*DHEAD;
    const float* kp = K + (size_t)bn*SEQ*DHEAD;
    const float* vp = V + (size_t)bn*SEQ*DHEAD;

    // stage Q (128x64) then build scaled tf32 fragments
    #pragma unroll
    for (int i = 0; i < 8; i++) {
        int f = tid + 256*i;
        int rr = f >> 4, c4 = (f & 15)*4;
        *(float4*)&Qstage[rr*FPAD + c4] = *(const float4*)&q[(size_t)rr*DHEAD + c4];
    }
    __syncthreads();
    uint32_t qf[8][4];
    #pragma unroll
    for (int ks = 0; ks < 8; ks++) {
        const float* p = &Qstage[(wr + r)*FPAD + ks*8 + qd];
        qf[ks][0] = f2tf(p[0]        * 0.125f);
        qf[ks][1] = f2tf(p[8*FPAD]   * 0.125f);
        qf[ks][2] = f2tf(p[4]        * 0.125f);
        qf[ks][3] = f2tf(p[8*FPAD+4] * 0.125f);
    }

    float m0 = -1e30f, m1 = -1e30f, l0 = 0.f, l1 = 0.f;
    float oacc[8][4];
    #pragma unroll
    for (int nt = 0; nt < 8; nt++)
        #pragma unroll
        for (int j = 0; j < 4; j++) oacc[nt][j] = 0.f;

    for (int j0 = 0; j0 < SEQ; j0 += 64) {
        __syncthreads();   // prior O-mma done with Vt; Q staging done (iter 0)

        // K tile: coalesced LDG, cvt, STS [j][d]
        #pragma unroll
        for (int i = 0; i < 4; i++) {
            int f = tid + 256*i;
            int jr = f >> 4, c4 = (f & 15)*4;
            float4 kv = *(const float4*)&kp[(size_t)(j0 + jr)*DHEAD + c4];
            uint32_t* dsp = &Ks[jr*FPAD + c4];
            dsp[0] = f2tf(kv.x); dsp[1] = f2tf(kv.y);
            dsp[2] = f2tf(kv.z); dsp[3] = f2tf(kv.w);
        }
        // V tile transposed: strided LDG V[j][d0..3], scatter STS Vt[d][j] (conflict-free)
        #pragma unroll
        for (int i = 0; i < 4; i++) {
            int f = tid + 256*i;
            int j = f & 63, d0 = (f >> 6)*4;
            float4 vv = *(const float4*)&vp[(size_t)(j0 + j)*DHEAD + d0];
            Vt[(d0+0)*FPAD + j] = f2tf(vv.x);
            Vt[(d0+1)*FPAD + j] = f2tf(vv.y);
            Vt[(d0+2)*FPAD + j] = f2tf(vv.z);
            Vt[(d0+3)*FPAD + j] = f2tf(vv.w);
        }
        __syncthreads();

        // S = (Q*scale) K^T -> sacc[8][4]
        float sacc[8][4];
        #pragma unroll
        for (int nt = 0; nt < 8; nt++)
            #pragma unroll
            for (int j = 0; j < 4; j++) sacc[nt][j] = 0.f;
        #pragma unroll
        for (int ks = 0; ks < 8; ks++) {
            uint32_t bfr[8][2];
            #pragma unroll
            for (int nt = 0; nt < 8; nt++) {
                const uint32_t* p = &Ks[(nt*8 + r)*FPAD + ks*8 + qd];
                bfr[nt][0] = p[0]; bfr[nt][1] = p[4];
            }
            #pragma unroll
            for (int nt = 0; nt < 8; nt++) mma_tf32(sacc[nt], qf[ks], bfr[nt]);
        }

        // online softmax: row r -> (c0,c1), row r+8 -> (c2,c3)
        float mx0 = -1e30f, mx1 = -1e30f;
        #pragma unroll
        for (int nt = 0; nt < 8; nt++) {
            mx0 = fmaxf(mx0, fmaxf(sacc[nt][0], sacc[nt][1]));
            mx1 = fmaxf(mx1, fmaxf(sacc[nt][2], sacc[nt][3]));
        }
        mx0 = fmaxf(mx0, __shfl_xor_sync(0xffffffffu, mx0, 1));
        mx0 = fmaxf(mx0, __shfl_xor_sync(0xffffffffu, mx0, 2));
        mx1 = fmaxf(mx1, __shfl_xor_sync(0xffffffffu, mx1, 1));
        mx1 = fmaxf(mx1, __shfl_xor_sync(0xffffffffu, mx1, 2));
        float nm0 = fmaxf(m0, mx0), nm1 = fmaxf(m1, mx1);
        float a0 = __expf(m0 - nm0), a1 = __expf(m1 - nm1);
        float rs0 = 0.f, rs1 = 0.f;
        #pragma unroll
        for (int nt = 0; nt < 8; nt++) {
            float p0 = __expf(sacc[nt][0] - nm0);
            float p1 = __expf(sacc[nt][1] - nm0);
            float p2 = __expf(sacc[nt][2] - nm1);
            float p3 = __expf(sacc[nt][3] - nm1);
            rs0 += p0 + p1; rs1 += p2 + p3;
            uint2 u0 = make_uint2(f2tf(p0), f2tf(p1));
            uint2 u1 = make_uint2(f2tf(p2), f2tf(p3));
            *(uint2*)&Ps[(wr + r    )*FPAD + nt*8 + 2*qd] = u0;
            *(uint2*)&Ps[(wr + r + 8)*FPAD + nt*8 + 2*qd] = u1;
        }
        rs0 += __shfl_xor_sync(0xffffffffu, rs0, 1);
        rs0 += __shfl_xor_sync(0xffffffffu, rs0, 2);
        rs1 += __shfl_xor_sync(0xffffffffu, rs1, 1);
        rs1 += __shfl_xor_sync(0xffffffffu, rs1, 2);
        m0 = nm0; m1 = nm1;
        l0 = l0*a0 + rs0; l1 = l1*a1 + rs1;
        #pragma unroll
        for (int nt = 0; nt < 8; nt++) {
            oacc[nt][0] *= a0; oacc[nt][1] *= a0;
            oacc[nt][2] *= a1; oacc[nt][3] *= a1;
        }
        __syncwarp();

        // O += P V  (A = Ps own rows, B = Vt)
        #pragma unroll
        for (int ks = 0; ks < 8; ks++) {
            uint32_t af[4];
            const uint32_t* pa = &Ps[(wr + r)*FPAD + ks*8 + qd];
            af[0] = pa[0]; af[1] = pa[8*FPAD]; af[2] = pa[4]; af[3] = pa[8*FPAD + 4];
            uint32_t bfr[8][2];
            #pragma unroll
            for (int nt = 0; nt < 8; nt++) {
                const uint32_t* p = &Vt[(nt*8 + r)*FPAD + ks*8 + qd];
                bfr[nt][0] = p[0]; bfr[nt][1] = p[4];
            }
            #pragma unroll
            for (int nt = 0; nt < 8; nt++) mma_tf32(oacc[nt], af, bfr[nt]);
        }
    }

    // epilogue -> AV row-major (i*BATCH+b)*DMODEL + nh*64 + d
    const float inv0 = 1.f / l0, inv1 = 1.f / l1;
    const int b = bn >> 4, nh = bn & 15;
    float* outp = AV + (size_t)strm*ROWS*DMODEL;
    const int ir0 = i0 + wr + r, ir1 = ir0 + 8;
    #pragma unroll
    for (int nt = 0; nt < 8; nt++) {
        int col = nh*DHEAD + nt*8 + 2*qd;
        float2 v0 = make_float2(oacc[nt][0]*inv0, oacc[nt][1]*inv0);
        float2 v1 = make_float2(oacc[nt][2]*inv1, oacc[nt][3]*inv1);
        *(float2*)&outp[(size_t)(ir0*BATCH + b)*DMODEL + col] = v0;
        *(float2*)&outp[(size_t)(ir1*BATCH + b)*DMODEL + col] = v1;
    }
}

// ---------------- residual + layernorm ----------------
__global__ __launch_bounds__(256)
void resid_ln(const float* __restrict__ AO, const float* __restrict__ h,
              const float* __restrict__ g, const float* __restrict__ gamma,
              const float* __restrict__ beta, float* __restrict__ out) {
    const int row = blockIdx.x;
    const int strm = blockIdx.y;
    const int tid = threadIdx.x;
    const float* x = (strm == 0) ? h : g;
    const float* ao = AO + (size_t)strm*ROWS*DMODEL + (size_t)row*DMODEL;
    const float* xr = x + (size_t)row*DMODEL;

    float4 a4 = *(const float4*)&ao[tid*4];
    float4 x4 = *(const float4*)&xr[tid*4];
    float y[4] = { a4.x + x4.x, a4.y + x4.y, a4.z + x4.z, a4.w + x4.w };

    float s1 = y[0] + y[1] + y[2] + y[3];
    float s2 = y[0]*y[0] + y[1]*y[1] + y[2]*y[2] + y[3]*y[3];
    #pragma unroll
    for (int off = 16; off > 0; off >>= 1) {
        s1 += __shfl_xor_sync(0xffffffffu, s1, off);
        s2 += __shfl_xor_sync(0xffffffffu, s2, off);
    }
    __shared__ float red[18];
    int warp = tid >> 5, lane = tid & 31;
    if (lane == 0) { red[warp*2] = s1; red[warp*2 + 1] = s2; }
    __syncthreads();
    if (tid == 0) {
        float t1 = 0.f, t2 = 0.f;
        #pragma unroll
        for (int w = 0; w < 8; w++) { t1 += red[w*2]; t2 += red[w*2 + 1]; }
        float mu = t1 * (1.f/DMODEL);
        float var = t2 * (1.f/DMODEL) - mu*mu;
        red[16] = mu;
        red[17] = rsqrtf(var + LN_EPS);
    }
    __syncthreads();
    float mu = red[16], inv = red[17];

    float4 g4 = *(const float4*)&gamma[tid*4];
    float4 b4 = *(const float4*)&beta[tid*4];
    float4 o;
    o.x = g4.x*(y[0] - mu)*inv + b4.x;
    o.y = g4.y*(y[1] - mu)*inv + b4.y;
    o.z = g4.z*(y[2] - mu)*inv + b4.z;
    o.w = g4.w*(y[3] - mu)*inv + b4.w;
    *(float4*)&out[(size_t)strm*ROWS*DMODEL + (size_t)row*DMODEL + tid*4] = o;
}

// ---------------- launch ----------------
extern "C" void kernel_launch(void* const* d_in, const int* in_sizes, int n_in,
                              void* d_out, int out_size) {
    const float* h     = (const float*)d_in[0];
    const float* g     = (const float*)d_in[1];
    const float* Wq    = (const float*)d_in[2];
    const float* Wk    = (const float*)d_in[3];
    const float* Wv    = (const float*)d_in[4];
    const float* Wo    = (const float*)d_in[5];
    const float* rwb   = (const float*)d_in[6];
    const float* gamma = (const float*)d_in[7];
    const float* beta  = (const float*)d_in[8];
    float* out = (float*)d_out;

    float *pK, *pV, *pQ, *pAV, *pAO, *pWqT, *pWkT, *pWvT;
    cudaGetSymbolAddress((void**)&pK,   g_K);
    cudaGetSymbolAddress((void**)&pV,   g_V);
    cudaGetSymbolAddress((void**)&pQ,   g_Q);
    cudaGetSymbolAddress((void**)&pAV,  g_AV);
    cudaGetSymbolAddress((void**)&pAO,  g_AO);
    cudaGetSymbolAddress((void**)&pWqT, g_WqT);
    cudaGetSymbolAddress((void**)&pWkT, g_WkT);
    cudaGetSymbolAddress((void**)&pWvT, g_WvT);

    cudaFuncSetAttribute(mma_gemm, cudaFuncAttributeMaxDynamicSharedMemorySize, GSMEM);
    cudaFuncSetAttribute(flash_mma, cudaFuncAttributeMaxDynamicSharedMemorySize, FSMEM);

    transpose1024<<<dim3(32, 32), dim3(32, 8)>>>(Wq, pWqT);
    transpose1024<<<dim3(32, 32), dim3(32, 8)>>>(Wk, pWkT);
    transpose1024<<<dim3(32, 32), dim3(32, 8)>>>(Wv, pWvT);

    dim3 ggrid(8, 32);
    mma_gemm<<<ggrid, 256, GSMEM>>>(h, pWkT, pK, nullptr, 1);
    mma_gemm<<<ggrid, 256, GSMEM>>>(h, pWvT, pV, nullptr, 1);
    mma_gemm<<<ggrid, 256, GSMEM>>>(h, pWqT, pQ, rwb, 2);
    mma_gemm<<<ggrid, 256, GSMEM>>>(g, pWqT, pQ + (size_t)BATCH*NHEAD*SEQ*DHEAD, rwb, 2);

    flash_mma<<<dim3(SEQ/128, BATCH*NHEAD, 2), 256, FSMEM>>>(pQ, pK, pV, pAV);

    mma_gemm<<<ggrid, 256, GSMEM>>>(pAV, Wo, pAO, nullptr, 0);
    mma_gemm<<<ggrid, 256, GSMEM>>>(pAV + (size_t)ROWS*DMODEL, Wo, pAO + (size_t)ROWS*DMODEL, nullptr, 0);

    resid_ln<<<dim3(ROWS, 2), 256>>>(pAO, h, g, gamma, beta, out);
}

// round 5
// speedup vs baseline: 3.3825x; 1.3223x over previous
#include <cuda_runtime.h>
#include <cuda_bf16.h>
#include <cstdint>
#include <math.h>

#define SEQ 2048
#define BATCH 2
#define NHEAD 16
#define DHEAD 64
#define DMODEL 1024
#define ROWS (SEQ*BATCH)          // 4096
#define LN_EPS 1e-5f

// ---------------- scratch (static device globals; no allocation) ----------------
__device__ __align__(16) float g_K[BATCH*NHEAD*SEQ*DHEAD];          // [b][n][i][d]
__device__ __align__(16) float g_V[BATCH*NHEAD*SEQ*DHEAD];
__device__ __align__(16) float g_Q[2*BATCH*NHEAD*SEQ*DHEAD];        // [stream][b][n][i][d]
__device__ __align__(16) float g_AO[2*ROWS*DMODEL];                 // attn_out pre-LN
__device__ __align__(16) __nv_bfloat16 g_AVb[2*ROWS*DMODEL];        // attn_vec bf16
__device__ __align__(16) __nv_bfloat16 g_hb[ROWS*DMODEL];           // h bf16
__device__ __align__(16) __nv_bfloat16 g_gb[ROWS*DMODEL];           // g bf16
__device__ __align__(16) __nv_bfloat16 g_WqTb[DMODEL*DMODEL];       // [n][k] bf16
__device__ __align__(16) __nv_bfloat16 g_WkTb[DMODEL*DMODEL];
__device__ __align__(16) __nv_bfloat16 g_WvTb[DMODEL*DMODEL];
__device__ __align__(16) __nv_bfloat16 g_Wob[DMODEL*DMODEL];        // Wo as-is, bf16

// ================= PTX helpers (base sm_103 target only) =================
__device__ __forceinline__ uint32_t s2u(const void* p) {
    uint32_t a;
    asm("{ .reg .u64 t; cvta.to.shared.u64 t, %1; cvt.u32.u64 %0, t; }" : "=r"(a) : "l"(p));
    return a;
}
#define CP_ASYNC16(dst, src) asm volatile("cp.async.cg.shared.global [%0], [%1], 16;" :: "r"(dst), "l"(src))
#define CP_COMMIT()  asm volatile("cp.async.commit_group;")
#define CP_WAIT1()   asm volatile("cp.async.wait_group 1;" ::: "memory")
#define CP_WAIT0()   asm volatile("cp.async.wait_group 0;" ::: "memory")

__device__ __forceinline__ uint32_t f2tf(float f) {
    uint32_t u;
    asm("cvt.rna.tf32.f32 %0, %1;" : "=r"(u) : "f"(f));
    return u;
}
__device__ __forceinline__ void mma_tf32(float* d, const uint32_t* a, const uint32_t* b) {
    asm volatile("mma.sync.aligned.m16n8k8.row.col.f32.tf32.tf32.f32 "
        "{%0,%1,%2,%3},{%4,%5,%6,%7},{%8,%9},{%0,%1,%2,%3};"
        : "+f"(d[0]), "+f"(d[1]), "+f"(d[2]), "+f"(d[3])
        : "r"(a[0]), "r"(a[1]), "r"(a[2]), "r"(a[3]), "r"(b[0]), "r"(b[1]));
}
__device__ __forceinline__ void mma_bf16(float* d, const uint32_t* a, uint32_t b0, uint32_t b1) {
    asm volatile("mma.sync.aligned.m16n8k16.row.col.f32.bf16.bf16.f32 "
        "{%0,%1,%2,%3},{%4,%5,%6,%7},{%8,%9},{%0,%1,%2,%3};"
        : "+f"(d[0]), "+f"(d[1]), "+f"(d[2]), "+f"(d[3])
        : "r"(a[0]), "r"(a[1]), "r"(a[2]), "r"(a[3]), "r"(b0), "r"(b1));
}
__device__ __forceinline__ void ldsm4(uint32_t* r, uint32_t addr) {
    asm volatile("ldmatrix.sync.aligned.m8n8.x4.shared.b16 {%0,%1,%2,%3}, [%4];"
        : "=r"(r[0]), "=r"(r[1]), "=r"(r[2]), "=r"(r[3]) : "r"(addr));
}

// ---------------- fp32 -> bf16 elementwise ----------------
__global__ void conv_f2b(const float* __restrict__ in, __nv_bfloat16* __restrict__ out) {
    int i = (blockIdx.x*blockDim.x + threadIdx.x)*4;
    float4 v = *(const float4*)&in[i];
    *(__nv_bfloat162*)&out[i]   = __floats2bfloat162_rn(v.x, v.y);
    *(__nv_bfloat162*)&out[i+2] = __floats2bfloat162_rn(v.z, v.w);
}

// ---------------- transpose+convert: out[n][k] = bf16(in[k][n]) ----------------
__global__ void transposeb(const float* __restrict__ in, __nv_bfloat16* __restrict__ out) {
    __shared__ float t[32][33];
    int x = blockIdx.x*32 + threadIdx.x;
    int y = blockIdx.y*32 + threadIdx.y;
    #pragma unroll
    for (int i = 0; i < 32; i += 8)
        t[threadIdx.y + i][threadIdx.x] = in[(size_t)(y + i)*DMODEL + x];
    __syncthreads();
    x = blockIdx.y*32 + threadIdx.x;
    y = blockIdx.x*32 + threadIdx.y;
    #pragma unroll
    for (int i = 0; i < 32; i += 8)
        out[(size_t)(y + i)*DMODEL + x] = __float2bfloat16(t[threadIdx.x][threadIdx.y + i]);
}

// ---------------- bf16 mma.sync GEMM: C[4096x1024] = A * BT^T ----------------
// A [M][K] bf16 row-major, BT [N][K] bf16 row-major. CTA 128x128, K-chunk 32.
// 8 warps: wm=warp&3 (32 rows), wn=warp>>2 (64 cols). ldmatrix fragments.
// mode 0: dst row-major fp32; mode 1: head-layout; mode 2: mode1 + bias
#define BPAD 40                      // bf16 per smem row (80 B)
#define BTB  (128*BPAD*2)            // bytes per tile buffer = 10240
#define BSMEM (4*BTB)                // A0,A1,B0,B1 = 40960 B

__global__ __launch_bounds__(256, 2)
void bgemm(const __nv_bfloat16* __restrict__ A, const __nv_bfloat16* __restrict__ BT,
           float* __restrict__ dst, const float* __restrict__ bias, int mode) {
    extern __shared__ char bsm[];
    const uint32_t sbase = s2u(bsm);

    const int tid  = threadIdx.x;
    const int lane = tid & 31, warp = tid >> 5;
    const int wm = warp & 3, wn = warp >> 2;
    const int br = blockIdx.y, bc = blockIdx.x;

    // cp.async slots: f = tid + 256*i -> row = f>>2 (0..127), seg = f&3 (16B each)
    const __nv_bfloat16* srcA[2]; const __nv_bfloat16* srcB[2]; uint32_t doff[2];
    #pragma unroll
    for (int i = 0; i < 2; i++) {
        int f = tid + 256*i;
        int row = f >> 2, seg = f & 3;
        srcA[i] = A  + (size_t)(br*128 + row)*DMODEL + seg*8;
        srcB[i] = BT + (size_t)(bc*128 + row)*DMODEL + seg*8;
        doff[i] = (uint32_t)(row*80 + seg*16);
    }

    auto load_chunk = [&](int c) {
        int buf = c & 1;
        uint32_t ab = sbase + buf*BTB;
        uint32_t bb = sbase + 2*BTB + buf*BTB;
        int kb = c * 32;
        #pragma unroll
        for (int i = 0; i < 2; i++) {
            CP_ASYNC16(ab + doff[i], (const void*)(srcA[i] + kb));
            CP_ASYNC16(bb + doff[i], (const void*)(srcB[i] + kb));
        }
        CP_COMMIT();
    };

    float d[2][8][4];
    #pragma unroll
    for (int mt = 0; mt < 2; mt++)
        #pragma unroll
        for (int nt = 0; nt < 8; nt++)
            #pragma unroll
            for (int j = 0; j < 4; j++) d[mt][nt][j] = 0.f;

    load_chunk(0);
    load_chunk(1);

    const int lg = lane >> 3, lr = lane & 7;      // ldmatrix group / row-in-group
    const int rsel = (lg & 1)*8 + lr;             // row offset within 16
    const int csel = (lg >> 1)*8;                 // col offset within 16 (bf16 elems)

    for (int c = 0; c < 32; c++) {
        if (c == 31) { CP_WAIT0(); } else { CP_WAIT1(); }
        __syncthreads();
        int buf = c & 1;
        uint32_t Abase = sbase + buf*BTB;
        uint32_t Bbase = sbase + 2*BTB + buf*BTB;

        #pragma unroll
        for (int ks = 0; ks < 2; ks++) {
            uint32_t af[2][4];
            #pragma unroll
            for (int mt = 0; mt < 2; mt++)
                ldsm4(af[mt], Abase + (uint32_t)((wm*32 + mt*16 + rsel)*80 + (ks*16 + csel)*2));
            uint32_t bf[4][4];
            #pragma unroll
            for (int n2 = 0; n2 < 4; n2++)
                ldsm4(bf[n2], Bbase + (uint32_t)((wn*64 + n2*16 + rsel)*80 + (ks*16 + csel)*2));
            #pragma unroll
            for (int mt = 0; mt < 2; mt++)
                #pragma unroll
                for (int n2 = 0; n2 < 4; n2++) {
                    mma_bf16(d[mt][2*n2],   af[mt], bf[n2][0], bf[n2][2]);
                    mma_bf16(d[mt][2*n2+1], af[mt], bf[n2][1], bf[n2][3]);
                }
        }
        __syncthreads();
        if (c + 2 < 32) load_chunk(c + 2);
    }

    const int r0 = wm*32 + (lane >> 2);
    const int cb = wn*64 + 2*(lane & 3);
    #pragma unroll
    for (int mt = 0; mt < 2; mt++) {
        #pragma unroll
        for (int rh = 0; rh < 2; rh++) {
            int row_g = br*128 + r0 + mt*16 + rh*8;
            #pragma unroll
            for (int nt = 0; nt < 8; nt++) {
                int col_g = bc*128 + cb + nt*8;
                float2 v = make_float2(d[mt][nt][2*rh], d[mt][nt][2*rh + 1]);
                if (mode == 0) {
                    *(float2*)&dst[(size_t)row_g*DMODEL + col_g] = v;
                } else {
                    if (mode == 2) {
                        v.x += bias[col_g];
                        v.y += bias[col_g + 1];
                    }
                    int i = row_g >> 1, b = row_g & 1;
                    int nh = col_g >> 6, dd = col_g & 63;
                    *(float2*)&dst[((size_t)(b*NHEAD + nh)*SEQ + i)*DHEAD + dd] = v;
                }
            }
        }
    }
}

// ---------------- flash attention on mma.sync tf32 (writes bf16 AV) ----------------
#define FPAD 68
#define FSMEM ((64*FPAD + 64*FPAD + 128*FPAD)*4)   // 69632 B

__global__ __launch_bounds__(256)
void flash_mma(const float* __restrict__ Qall, const float* __restrict__ K,
               const float* __restrict__ V, __nv_bfloat16* __restrict__ AVb) {
    extern __shared__ uint32_t fsm[];
    uint32_t* Ks = fsm;                  // 64*FPAD
    uint32_t* Vt = fsm + 64*FPAD;        // 64*FPAD
    uint32_t* Ps = fsm + 128*FPAD;       // 128*FPAD
    float* Qstage = (float*)Ps;

    const int tid = threadIdx.x, lane = tid & 31, warp = tid >> 5;
    const int r = lane >> 2, qd = lane & 3;
    const int wr = warp*16;
    const int i0 = blockIdx.x*128;
    const int bn = blockIdx.y, strm = blockIdx.z;

    const float* q  = Qall + ((size_t)strm*BATCH*NHEAD + bn)*SEQ*DHEAD + (size_t)i0*DHEAD;
    const float* kp = K + (size_t)bn*SEQ*DHEAD;
    const float* vp = V + (size_t)bn*SEQ*DHEAD;

    #pragma unroll
    for (int i = 0; i < 8; i++) {
        int f = tid + 256*i;
        int rr = f >> 4, c4 = (f & 15)*4;
        *(float4*)&Qstage[rr*FPAD + c4] = *(const float4*)&q[(size_t)rr*DHEAD + c4];
    }
    __syncthreads();
    uint32_t qf[8][4];
    #pragma unroll
    for (int ks = 0; ks < 8; ks++) {
        const float* p = &Qstage[(wr + r)*FPAD + ks*8 + qd];
        qf[ks][0] = f2tf(p[0]        * 0.125f);
        qf[ks][1] = f2tf(p[8*FPAD]   * 0.125f);
        qf[ks][2] = f2tf(p[4]        * 0.125f);
        qf[ks][3] = f2tf(p[8*FPAD+4] * 0.125f);
    }

    float m0 = -1e30f, m1 = -1e30f, l0 = 0.f, l1 = 0.f;
    float oacc[8][4];
    #pragma unroll
    for (int nt = 0; nt < 8; nt++)
        #pragma unroll
        for (int j = 0; j < 4; j++) oacc[nt][j] = 0.f;

    for (int j0 = 0; j0 < SEQ; j0 += 64) {
        __syncthreads();

        #pragma unroll
        for (int i = 0; i < 4; i++) {
            int f = tid + 256*i;
            int jr = f >> 4, c4 = (f & 15)*4;
            float4 kv = *(const float4*)&kp[(size_t)(j0 + jr)*DHEAD + c4];
            uint32_t* dsp = &Ks[jr*FPAD + c4];
            dsp[0] = f2tf(kv.x); dsp[1] = f2tf(kv.y);
            dsp[2] = f2tf(kv.z); dsp[3] = f2tf(kv.w);
        }
        #pragma unroll
        for (int i = 0; i < 4; i++) {
            int f = tid + 256*i;
            int j = f & 63, d0 = (f >> 6)*4;
            float4 vv = *(const float4*)&vp[(size_t)(j0 + j)*DHEAD + d0];
            Vt[(d0+0)*FPAD + j] = f2tf(vv.x);
            Vt[(d0+1)*FPAD + j] = f2tf(vv.y);
            Vt[(d0+2)*FPAD + j] = f2tf(vv.z);
            Vt[(d0+3)*FPAD + j] = f2tf(vv.w);
        }
        __syncthreads();

        float sacc[8][4];
        #pragma unroll
        for (int nt = 0; nt < 8; nt++)
            #pragma unroll
            for (int j = 0; j < 4; j++) sacc[nt][j] = 0.f;
        #pragma unroll
        for (int ks = 0; ks < 8; ks++) {
            uint32_t bfr[8][2];
            #pragma unroll
            for (int nt = 0; nt < 8; nt++) {
                const uint32_t* p = &Ks[(nt*8 + r)*FPAD + ks*8 + qd];
                bfr[nt][0] = p[0]; bfr[nt][1] = p[4];
            }
            #pragma unroll
            for (int nt = 0; nt < 8; nt++) mma_tf32(sacc[nt], qf[ks], bfr[nt]);
        }

        float mx0 = -1e30f, mx1 = -1e30f;
        #pragma unroll
        for (int nt = 0; nt < 8; nt++) {
            mx0 = fmaxf(mx0, fmaxf(sacc[nt][0], sacc[nt][1]));
            mx1 = fmaxf(mx1, fmaxf(sacc[nt][2], sacc[nt][3]));
        }
        mx0 = fmaxf(mx0, __shfl_xor_sync(0xffffffffu, mx0, 1));
        mx0 = fmaxf(mx0, __shfl_xor_sync(0xffffffffu, mx0, 2));
        mx1 = fmaxf(mx1, __shfl_xor_sync(0xffffffffu, mx1, 1));
        mx1 = fmaxf(mx1, __shfl_xor_sync(0xffffffffu, mx1, 2));
        float nm0 = fmaxf(m0, mx0), nm1 = fmaxf(m1, mx1);
        float a0 = __expf(m0 - nm0), a1 = __expf(m1 - nm1);
        float rs0 = 0.f, rs1 = 0.f;
        #pragma unroll
        for (int nt = 0; nt < 8; nt++) {
            float p0 = __expf(sacc[nt][0] - nm0);
            float p1 = __expf(sacc[nt][1] - nm0);
            float p2 = __expf(sacc[nt][2] - nm1);
            float p3 = __expf(sacc[nt][3] - nm1);
            rs0 += p0 + p1; rs1 += p2 + p3;
            uint2 u0 = make_uint2(f2tf(p0), f2tf(p1));
            uint2 u1 = make_uint2(f2tf(p2), f2tf(p3));
            *(uint2*)&Ps[(wr + r    )*FPAD + nt*8 + 2*qd] = u0;
            *(uint2*)&Ps[(wr + r + 8)*FPAD + nt*8 + 2*qd] = u1;
        }
        rs0 += __shfl_xor_sync(0xffffffffu, rs0, 1);
        rs0 += __shfl_xor_sync(0xffffffffu, rs0, 2);
        rs1 += __shfl_xor_sync(0xffffffffu, rs1, 1);
        rs1 += __shfl_xor_sync(0xffffffffu, rs1, 2);
        m0 = nm0; m1 = nm1;
        l0 = l0*a0 + rs0; l1 = l1*a1 + rs1;
        #pragma unroll
        for (int nt = 0; nt < 8; nt++) {
            oacc[nt][0] *= a0; oacc[nt][1] *= a0;
            oacc[nt][2] *= a1; oacc[nt][3] *= a1;
        }
        __syncwarp();

        #pragma unroll
        for (int ks = 0; ks < 8; ks++) {
            uint32_t af[4];
            const uint32_t* pa = &Ps[(wr + r)*FPAD + ks*8 + qd];
            af[0] = pa[0]; af[1] = pa[8*FPAD]; af[2] = pa[4]; af[3] = pa[8*FPAD + 4];
            uint32_t bfr[8][2];
            #pragma unroll
            for (int nt = 0; nt < 8; nt++) {
                const uint32_t* p = &Vt[(nt*8 + r)*FPAD + ks*8 + qd];
                bfr[nt][0] = p[0]; bfr[nt][1] = p[4];
            }
            #pragma unroll
            for (int nt = 0; nt < 8; nt++) mma_tf32(oacc[nt], af, bfr[nt]);
        }
    }

    const float inv0 = 1.f / l0, inv1 = 1.f / l1;
    const int b = bn >> 4, nh = bn & 15;
    __nv_bfloat16* outp = AVb + (size_t)strm*ROWS*DMODEL;
    const int ir0 = i0 + wr + r, ir1 = ir0 + 8;
    #pragma unroll
    for (int nt = 0; nt < 8; nt++) {
        int col = nh*DHEAD + nt*8 + 2*qd;
        *(__nv_bfloat162*)&outp[(size_t)(ir0*BATCH + b)*DMODEL + col] =
            __floats2bfloat162_rn(oacc[nt][0]*inv0, oacc[nt][1]*inv0);
        *(__nv_bfloat162*)&outp[(size_t)(ir1*BATCH + b)*DMODEL + col] =
            __floats2bfloat162_rn(oacc[nt][2]*inv1, oacc[nt][3]*inv1);
    }
}

// ---------------- residual + layernorm ----------------
__global__ __launch_bounds__(256)
void resid_ln(const float* __restrict__ AO, const float* __restrict__ h,
              const float* __restrict__ g, const float* __restrict__ gamma,
              const float* __restrict__ beta, float* __restrict__ out) {
    const int row = blockIdx.x;
    const int strm = blockIdx.y;
    const int tid = threadIdx.x;
    const float* x = (strm == 0) ? h : g;
    const float* ao = AO + (size_t)strm*ROWS*DMODEL + (size_t)row*DMODEL;
    const float* xr = x + (size_t)row*DMODEL;

    float4 a4 = *(const float4*)&ao[tid*4];
    float4 x4 = *(const float4*)&xr[tid*4];
    float y[4] = { a4.x + x4.x, a4.y + x4.y, a4.z + x4.z, a4.w + x4.w };

    float s1 = y[0] + y[1] + y[2] + y[3];
    float s2 = y[0]*y[0] + y[1]*y[1] + y[2]*y[2] + y[3]*y[3];
    #pragma unroll
    for (int off = 16; off > 0; off >>= 1) {
        s1 += __shfl_xor_sync(0xffffffffu, s1, off);
        s2 += __shfl_xor_sync(0xffffffffu, s2, off);
    }
    __shared__ float red[18];
    int warp = tid >> 5, lane = tid & 31;
    if (lane == 0) { red[warp*2] = s1; red[warp*2 + 1] = s2; }
    __syncthreads();
    if (tid == 0) {
        float t1 = 0.f, t2 = 0.f;
        #pragma unroll
        for (int w = 0; w < 8; w++) { t1 += red[w*2]; t2 += red[w*2 + 1]; }
        float mu = t1 * (1.f/DMODEL);
        float var = t2 * (1.f/DMODEL) - mu*mu;
        red[16] = mu;
        red[17] = rsqrtf(var + LN_EPS);
    }
    __syncthreads();
    float mu = red[16], inv = red[17];

    float4 g4 = *(const float4*)&gamma[tid*4];
    float4 b4 = *(const float4*)&beta[tid*4];
    float4 o;
    o.x = g4.x*(y[0] - mu)*inv + b4.x;
    o.y = g4.y*(y[1] - mu)*inv + b4.y;
    o.z = g4.z*(y[2] - mu)*inv + b4.z;
    o.w = g4.w*(y[3] - mu)*inv + b4.w;
    *(float4*)&out[(size_t)strm*ROWS*DMODEL + (size_t)row*DMODEL + tid*4] = o;
}

// ---------------- launch ----------------
extern "C" void kernel_launch(void* const* d_in, const int* in_sizes, int n_in,
                              void* d_out, int out_size) {
    const float* h     = (const float*)d_in[0];
    const float* g     = (const float*)d_in[1];
    const float* Wq    = (const float*)d_in[2];
    const float* Wk    = (const float*)d_in[3];
    const float* Wv    = (const float*)d_in[4];
    const float* Wo    = (const float*)d_in[5];
    const float* rwb   = (const float*)d_in[6];
    const float* gamma = (const float*)d_in[7];
    const float* beta  = (const float*)d_in[8];
    float* out = (float*)d_out;

    float *pK, *pV, *pQ, *pAO;
    __nv_bfloat16 *pAVb, *phb, *pgb, *pWqTb, *pWkTb, *pWvTb, *pWob;
    cudaGetSymbolAddress((void**)&pK,    g_K);
    cudaGetSymbolAddress((void**)&pV,    g_V);
    cudaGetSymbolAddress((void**)&pQ,    g_Q);
    cudaGetSymbolAddress((void**)&pAO,   g_AO);
    cudaGetSymbolAddress((void**)&pAVb,  g_AVb);
    cudaGetSymbolAddress((void**)&phb,   g_hb);
    cudaGetSymbolAddress((void**)&pgb,   g_gb);
    cudaGetSymbolAddress((void**)&pWqTb, g_WqTb);
    cudaGetSymbolAddress((void**)&pWkTb, g_WkTb);
    cudaGetSymbolAddress((void**)&pWvTb, g_WvTb);
    cudaGetSymbolAddress((void**)&pWob,  g_Wob);

    cudaFuncSetAttribute(bgemm, cudaFuncAttributeMaxDynamicSharedMemorySize, BSMEM);
    cudaFuncSetAttribute(flash_mma, cudaFuncAttributeMaxDynamicSharedMemorySize, FSMEM);

    // input/weight conversions
    conv_f2b<<<ROWS*DMODEL/1024, 256>>>(h, phb);
    conv_f2b<<<ROWS*DMODEL/1024, 256>>>(g, pgb);
    conv_f2b<<<DMODEL*DMODEL/1024, 256>>>(Wo, pWob);
    transposeb<<<dim3(32, 32), dim3(32, 8)>>>(Wq, pWqTb);
    transposeb<<<dim3(32, 32), dim3(32, 8)>>>(Wk, pWkTb);
    transposeb<<<dim3(32, 32), dim3(32, 8)>>>(Wv, pWvTb);

    dim3 ggrid(8, 32);
    bgemm<<<ggrid, 256, BSMEM>>>(phb, pWkTb, pK, nullptr, 1);
    bgemm<<<ggrid, 256, BSMEM>>>(phb, pWvTb, pV, nullptr, 1);
    bgemm<<<ggrid, 256, BSMEM>>>(phb, pWqTb, pQ, rwb, 2);
    bgemm<<<ggrid, 256, BSMEM>>>(pgb, pWqTb, pQ + (size_t)BATCH*NHEAD*SEQ*DHEAD, rwb, 2);

    flash_mma<<<dim3(SEQ/128, BATCH*NHEAD, 2), 256, FSMEM>>>(pQ, pK, pV, pAVb);

    bgemm<<<ggrid, 256, BSMEM>>>(pAVb, pWob, pAO, nullptr, 0);
    bgemm<<<ggrid, 256, BSMEM>>>(pAVb + (size_t)ROWS*DMODEL, pWob, pAO + (size_t)ROWS*DMODEL, nullptr, 0);

    resid_ln<<<dim3(ROWS, 2), 256>>>(pAO, h, g, gamma, beta, out);
}

// round 6
// speedup vs baseline: 5.5728x; 1.6475x over previous
#include <cuda_runtime.h>
#include <cuda_bf16.h>
#include <cstdint>
#include <math.h>

#define SEQ 2048
#define BATCH 2
#define NHEAD 16
#define DHEAD 64
#define DMODEL 1024
#define ROWS (SEQ*BATCH)          // 4096
#define LN_EPS 1e-5f

// ---------------- scratch (static device globals; no allocation) ----------------
__device__ __align__(16) __nv_bfloat16 g_Kb[BATCH*NHEAD*SEQ*DHEAD];   // [b][n][j][d]
__device__ __align__(16) __nv_bfloat16 g_Vb[BATCH*NHEAD*SEQ*DHEAD];   // [b][n][j][d]
__device__ __align__(16) __nv_bfloat16 g_Qb[2*BATCH*NHEAD*SEQ*DHEAD]; // [s][b][n][i][d]
__device__ __align__(16) float g_AO[2*ROWS*DMODEL];                 // attn_out pre-LN
__device__ __align__(16) __nv_bfloat16 g_AVb[2*ROWS*DMODEL];        // attn_vec bf16
__device__ __align__(16) __nv_bfloat16 g_hb[ROWS*DMODEL];
__device__ __align__(16) __nv_bfloat16 g_gb[ROWS*DMODEL];
__device__ __align__(16) __nv_bfloat16 g_WqTb[DMODEL*DMODEL];       // [n][k]
__device__ __align__(16) __nv_bfloat16 g_WkTb[DMODEL*DMODEL];
__device__ __align__(16) __nv_bfloat16 g_WvTb[DMODEL*DMODEL];
__device__ __align__(16) __nv_bfloat16 g_Wob[DMODEL*DMODEL];

// ================= PTX helpers (base sm_103 target only) =================
__device__ __forceinline__ uint32_t s2u(const void* p) {
    uint32_t a;
    asm("{ .reg .u64 t; cvta.to.shared.u64 t, %1; cvt.u32.u64 %0, t; }" : "=r"(a) : "l"(p));
    return a;
}
#define CP_ASYNC16(dst, src) asm volatile("cp.async.cg.shared.global [%0], [%1], 16;" :: "r"(dst), "l"(src))
#define CP_COMMIT()  asm volatile("cp.async.commit_group;")
#define CP_WAIT1()   asm volatile("cp.async.wait_group 1;" ::: "memory")
#define CP_WAIT0()   asm volatile("cp.async.wait_group 0;" ::: "memory")

__device__ __forceinline__ void mma_bf16(float* d, const uint32_t* a, uint32_t b0, uint32_t b1) {
    asm volatile("mma.sync.aligned.m16n8k16.row.col.f32.bf16.bf16.f32 "
        "{%0,%1,%2,%3},{%4,%5,%6,%7},{%8,%9},{%0,%1,%2,%3};"
        : "+f"(d[0]), "+f"(d[1]), "+f"(d[2]), "+f"(d[3])
        : "r"(a[0]), "r"(a[1]), "r"(a[2]), "r"(a[3]), "r"(b0), "r"(b1));
}
__device__ __forceinline__ void ldsm4(uint32_t* r, uint32_t addr) {
    asm volatile("ldmatrix.sync.aligned.m8n8.x4.shared.b16 {%0,%1,%2,%3}, [%4];"
        : "=r"(r[0]), "=r"(r[1]), "=r"(r[2]), "=r"(r[3]) : "r"(addr));
}
__device__ __forceinline__ void ldsm4t(uint32_t* r, uint32_t addr) {
    asm volatile("ldmatrix.sync.aligned.m8n8.x4.trans.shared.b16 {%0,%1,%2,%3}, [%4];"
        : "=r"(r[0]), "=r"(r[1]), "=r"(r[2]), "=r"(r[3]) : "r"(addr));
}
__device__ __forceinline__ uint32_t packbf(float lo, float hi) {
    __nv_bfloat162 t = __floats2bfloat162_rn(lo, hi);
    return *(uint32_t*)&t;
}

// ---------------- fp32 -> bf16 elementwise ----------------
__global__ void conv_f2b(const float* __restrict__ in, __nv_bfloat16* __restrict__ out) {
    int i = (blockIdx.x*blockDim.x + threadIdx.x)*4;
    float4 v = *(const float4*)&in[i];
    *(__nv_bfloat162*)&out[i]   = __floats2bfloat162_rn(v.x, v.y);
    *(__nv_bfloat162*)&out[i+2] = __floats2bfloat162_rn(v.z, v.w);
}

// ---------------- transpose+convert: out[n][k] = bf16(in[k][n]) ----------------
__global__ void transposeb(const float* __restrict__ in, __nv_bfloat16* __restrict__ out) {
    __shared__ float t[32][33];
    int x = blockIdx.x*32 + threadIdx.x;
    int y = blockIdx.y*32 + threadIdx.y;
    #pragma unroll
    for (int i = 0; i < 32; i += 8)
        t[threadIdx.y + i][threadIdx.x] = in[(size_t)(y + i)*DMODEL + x];
    __syncthreads();
    x = blockIdx.y*32 + threadIdx.x;
    y = blockIdx.x*32 + threadIdx.y;
    #pragma unroll
    for (int i = 0; i < 32; i += 8)
        out[(size_t)(y + i)*DMODEL + x] = __float2bfloat16(t[threadIdx.x][threadIdx.y + i]);
}

// ---------------- bf16 mma.sync GEMM ----------------
// mode 0: fp32 row-major (dstf); mode 3: bf16 head layout (dstb); mode 4: mode3 + bias
#define BPAD 40
#define BTB  (128*BPAD*2)            // 10240 B per buffer
#define BSMEM (4*BTB)                // 40960 B

__global__ __launch_bounds__(256, 2)
void bgemm(const __nv_bfloat16* __restrict__ A, const __nv_bfloat16* __restrict__ BT,
           float* __restrict__ dstf, __nv_bfloat16* __restrict__ dstb,
           const float* __restrict__ bias, int mode) {
    extern __shared__ char bsm[];
    const uint32_t sbase = s2u(bsm);

    const int tid  = threadIdx.x;
    const int lane = tid & 31, warp = tid >> 5;
    const int wm = warp & 3, wn = warp >> 2;
    const int br = blockIdx.y, bc = blockIdx.x;

    const __nv_bfloat16* srcA[2]; const __nv_bfloat16* srcB[2]; uint32_t doff[2];
    #pragma unroll
    for (int i = 0; i < 2; i++) {
        int f = tid + 256*i;
        int row = f >> 2, seg = f & 3;
        srcA[i] = A  + (size_t)(br*128 + row)*DMODEL + seg*8;
        srcB[i] = BT + (size_t)(bc*128 + row)*DMODEL + seg*8;
        doff[i] = (uint32_t)(row*80 + seg*16);
    }

    auto load_chunk = [&](int c) {
        int buf = c & 1;
        uint32_t ab = sbase + buf*BTB;
        uint32_t bb = sbase + 2*BTB + buf*BTB;
        int kb = c * 32;
        #pragma unroll
        for (int i = 0; i < 2; i++) {
            CP_ASYNC16(ab + doff[i], (const void*)(srcA[i] + kb));
            CP_ASYNC16(bb + doff[i], (const void*)(srcB[i] + kb));
        }
        CP_COMMIT();
    };

    float d[2][8][4];
    #pragma unroll
    for (int mt = 0; mt < 2; mt++)
        #pragma unroll
        for (int nt = 0; nt < 8; nt++)
            #pragma unroll
            for (int j = 0; j < 4; j++) d[mt][nt][j] = 0.f;

    load_chunk(0);
    load_chunk(1);

    const int lg = lane >> 3, lr = lane & 7;
    const int rsel = (lg & 1)*8 + lr;
    const int csel = (lg >> 1)*8;

    for (int c = 0; c < 32; c++) {
        if (c == 31) { CP_WAIT0(); } else { CP_WAIT1(); }
        __syncthreads();
        int buf = c & 1;
        uint32_t Abase = sbase + buf*BTB;
        uint32_t Bbase = sbase + 2*BTB + buf*BTB;

        #pragma unroll
        for (int ks = 0; ks < 2; ks++) {
            uint32_t af[2][4];
            #pragma unroll
            for (int mt = 0; mt < 2; mt++)
                ldsm4(af[mt], Abase + (uint32_t)((wm*32 + mt*16 + rsel)*80 + (ks*16 + csel)*2));
            uint32_t bf[4][4];
            #pragma unroll
            for (int n2 = 0; n2 < 4; n2++)
                ldsm4(bf[n2], Bbase + (uint32_t)((wn*64 + n2*16 + rsel)*80 + (ks*16 + csel)*2));
            #pragma unroll
            for (int mt = 0; mt < 2; mt++)
                #pragma unroll
                for (int n2 = 0; n2 < 4; n2++) {
                    mma_bf16(d[mt][2*n2],   af[mt], bf[n2][0], bf[n2][2]);
                    mma_bf16(d[mt][2*n2+1], af[mt], bf[n2][1], bf[n2][3]);
                }
        }
        __syncthreads();
        if (c + 2 < 32) load_chunk(c + 2);
    }

    const int r0 = wm*32 + (lane >> 2);
    const int cb = wn*64 + 2*(lane & 3);
    #pragma unroll
    for (int mt = 0; mt < 2; mt++) {
        #pragma unroll
        for (int rh = 0; rh < 2; rh++) {
            int row_g = br*128 + r0 + mt*16 + rh*8;
            #pragma unroll
            for (int nt = 0; nt < 8; nt++) {
                int col_g = bc*128 + cb + nt*8;
                float2 v = make_float2(d[mt][nt][2*rh], d[mt][nt][2*rh + 1]);
                if (mode == 0) {
                    *(float2*)&dstf[(size_t)row_g*DMODEL + col_g] = v;
                } else {
                    if (mode == 4) {
                        v.x += bias[col_g];
                        v.y += bias[col_g + 1];
                    }
                    int i = row_g >> 1, b = row_g & 1;
                    int nh = col_g >> 6, dd = col_g & 63;
                    *(__nv_bfloat162*)&dstb[((size_t)(b*NHEAD + nh)*SEQ + i)*DHEAD + dd] =
                        __floats2bfloat162_rn(v.x, v.y);
                }
            }
        }
    }
}

// ---------------- flash attention, bf16 mma + ldmatrix ----------------
// grid (16, 32, 2), block 256 (8 warps x 16 rows of a 128-row Q tile), BN=64
// smem rows padded to 144 B. Layout: Qs[0,18432) K0[18432) V0[27648) K1[36864) V1[46080)
#define KPB 144
#define FBSMEM 55296

__global__ __launch_bounds__(256)
void flash_bf(const __nv_bfloat16* __restrict__ Qall, const __nv_bfloat16* __restrict__ Kg,
              const __nv_bfloat16* __restrict__ Vg, __nv_bfloat16* __restrict__ AVb) {
    extern __shared__ char fs[];
    const uint32_t sb = s2u(fs);
    const int tid = threadIdx.x, lane = tid & 31, warp = tid >> 5;
    const int r = lane >> 2, qd = lane & 3, lg = lane >> 3, lr = lane & 7;
    const int wr = warp*16;
    const int i0 = blockIdx.x*128, bn = blockIdx.y, strm = blockIdx.z;

    const __nv_bfloat16* q  = Qall + ((size_t)(strm*BATCH*NHEAD + bn)*SEQ + i0)*DHEAD;
    const __nv_bfloat16* kp = Kg + (size_t)bn*SEQ*DHEAD;
    const __nv_bfloat16* vp = Vg + (size_t)bn*SEQ*DHEAD;

    // Q stage (128 rows x 128B)
    #pragma unroll
    for (int i = 0; i < 4; i++) {
        int f = tid + 256*i;
        int row = f >> 3, seg = f & 7;
        CP_ASYNC16(sb + row*KPB + seg*16, (const void*)(q + row*64 + seg*8));
    }
    CP_COMMIT();

    auto load_tile = [&](int jt) {
        int buf = jt & 1, j0 = jt*64;
        uint32_t kb = sb + 18432 + buf*18432;
        uint32_t vb = kb + 9216;
        #pragma unroll
        for (int i = 0; i < 2; i++) {
            int f = tid + 256*i;
            int row = f >> 3, seg = f & 7;
            CP_ASYNC16(kb + row*KPB + seg*16, (const void*)(kp + (size_t)(j0+row)*64 + seg*8));
            CP_ASYNC16(vb + row*KPB + seg*16, (const void*)(vp + (size_t)(j0+row)*64 + seg*8));
        }
        CP_COMMIT();
    };
    load_tile(0);
    load_tile(1);

    CP_WAIT1();              // Q + tile0 resident
    __syncthreads();
    uint32_t qf[4][4];
    #pragma unroll
    for (int ks = 0; ks < 4; ks++)
        ldsm4(qf[ks], sb + (uint32_t)((wr + (lg&1)*8 + lr)*KPB + (ks*16 + (lg>>1)*8)*2));

    float m0 = -1e30f, m1 = -1e30f, l0 = 0.f, l1 = 0.f;
    float oacc[8][4];
    #pragma unroll
    for (int nt = 0; nt < 8; nt++)
        #pragma unroll
        for (int j = 0; j < 4; j++) oacc[nt][j] = 0.f;

    for (int jt = 0; jt < 32; jt++) {
        if (jt == 31) { CP_WAIT0(); } else { CP_WAIT1(); }
        __syncthreads();
        int buf = jt & 1;
        uint32_t kb = sb + 18432 + buf*18432;
        uint32_t vb = kb + 9216;

        // S = Q K^T (fp32 accum)
        float sacc[8][4];
        #pragma unroll
        for (int nt = 0; nt < 8; nt++)
            #pragma unroll
            for (int j = 0; j < 4; j++) sacc[nt][j] = 0.f;
        #pragma unroll
        for (int ks = 0; ks < 4; ks++) {
            uint32_t bfk[4][4];
            #pragma unroll
            for (int n2 = 0; n2 < 4; n2++)
                ldsm4(bfk[n2], kb + (uint32_t)((n2*16 + (lg&1)*8 + lr)*KPB + (ks*16 + (lg>>1)*8)*2));
            #pragma unroll
            for (int n2 = 0; n2 < 4; n2++) {
                mma_bf16(sacc[2*n2],   qf[ks], bfk[n2][0], bfk[n2][2]);
                mma_bf16(sacc[2*n2+1], qf[ks], bfk[n2][1], bfk[n2][3]);
            }
        }

        // scale + online softmax (rows r -> c0,c1 ; r+8 -> c2,c3)
        #pragma unroll
        for (int nt = 0; nt < 8; nt++)
            #pragma unroll
            for (int j = 0; j < 4; j++) sacc[nt][j] *= 0.125f;
        float mx0 = -1e30f, mx1 = -1e30f;
        #pragma unroll
        for (int nt = 0; nt < 8; nt++) {
            mx0 = fmaxf(mx0, fmaxf(sacc[nt][0], sacc[nt][1]));
            mx1 = fmaxf(mx1, fmaxf(sacc[nt][2], sacc[nt][3]));
        }
        mx0 = fmaxf(mx0, __shfl_xor_sync(0xffffffffu, mx0, 1));
        mx0 = fmaxf(mx0, __shfl_xor_sync(0xffffffffu, mx0, 2));
        mx1 = fmaxf(mx1, __shfl_xor_sync(0xffffffffu, mx1, 1));
        mx1 = fmaxf(mx1, __shfl_xor_sync(0xffffffffu, mx1, 2));
        float nm0 = fmaxf(m0, mx0), nm1 = fmaxf(m1, mx1);
        float a0 = __expf(m0 - nm0), a1 = __expf(m1 - nm1);
        float rs0 = 0.f, rs1 = 0.f;
        #pragma unroll
        for (int nt = 0; nt < 8; nt++) {
            sacc[nt][0] = __expf(sacc[nt][0] - nm0);
            sacc[nt][1] = __expf(sacc[nt][1] - nm0);
            sacc[nt][2] = __expf(sacc[nt][2] - nm1);
            sacc[nt][3] = __expf(sacc[nt][3] - nm1);
            rs0 += sacc[nt][0] + sacc[nt][1];
            rs1 += sacc[nt][2] + sacc[nt][3];
        }
        rs0 += __shfl_xor_sync(0xffffffffu, rs0, 1);
        rs0 += __shfl_xor_sync(0xffffffffu, rs0, 2);
        rs1 += __shfl_xor_sync(0xffffffffu, rs1, 1);
        rs1 += __shfl_xor_sync(0xffffffffu, rs1, 2);
        m0 = nm0; m1 = nm1;
        l0 = l0*a0 + rs0; l1 = l1*a1 + rs1;
        #pragma unroll
        for (int nt = 0; nt < 8; nt++) {
            oacc[nt][0] *= a0; oacc[nt][1] *= a0;
            oacc[nt][2] *= a1; oacc[nt][3] *= a1;
        }

        // P fragments straight from registers (S-accum layout == A-fragment layout)
        uint32_t paf[4][4];
        #pragma unroll
        for (int kt = 0; kt < 4; kt++) {
            paf[kt][0] = packbf(sacc[2*kt][0],   sacc[2*kt][1]);
            paf[kt][1] = packbf(sacc[2*kt][2],   sacc[2*kt][3]);
            paf[kt][2] = packbf(sacc[2*kt+1][0], sacc[2*kt+1][1]);
            paf[kt][3] = packbf(sacc[2*kt+1][2], sacc[2*kt+1][3]);
        }

        // O += P V  (V^T fragments via ldmatrix.trans on V[j][d])
        #pragma unroll
        for (int kt = 0; kt < 4; kt++) {
            uint32_t bfv[4][4];
            #pragma unroll
            for (int n2 = 0; n2 < 4; n2++)
                ldsm4t(bfv[n2], vb + (uint32_t)((kt*16 + (lg>>1)*8 + lr)*KPB + (n2*16 + (lg&1)*8)*2));
            #pragma unroll
            for (int n2 = 0; n2 < 4; n2++) {
                mma_bf16(oacc[2*n2],   paf[kt], bfv[n2][0], bfv[n2][2]);
                mma_bf16(oacc[2*n2+1], paf[kt], bfv[n2][1], bfv[n2][3]);
            }
        }

        __syncthreads();                 // all reads of buf done
        if (jt + 2 < 32) load_tile(jt + 2);
    }

    // epilogue -> AV bf16 row-major (i*BATCH+b)*DMODEL + nh*64 + d
    const float inv0 = 1.f / l0, inv1 = 1.f / l1;
    const int b = bn >> 4, nh = bn & 15;
    __nv_bfloat16* outp = AVb + (size_t)strm*ROWS*DMODEL;
    const int ir0 = i0 + wr + r, ir1 = ir0 + 8;
    #pragma unroll
    for (int nt = 0; nt < 8; nt++) {
        int col = nh*DHEAD + nt*8 + 2*qd;
        *(__nv_bfloat162*)&outp[(size_t)(ir0*BATCH + b)*DMODEL + col] =
            __floats2bfloat162_rn(oacc[nt][0]*inv0, oacc[nt][1]*inv0);
        *(__nv_bfloat162*)&outp[(size_t)(ir1*BATCH + b)*DMODEL + col] =
            __floats2bfloat162_rn(oacc[nt][2]*inv1, oacc[nt][3]*inv1);
    }
}

// ---------------- residual + layernorm ----------------
__global__ __launch_bounds__(256)
void resid_ln(const float* __restrict__ AO, const float* __restrict__ h,
              const float* __restrict__ g, const float* __restrict__ gamma,
              const float* __restrict__ beta, float* __restrict__ out) {
    const int row = blockIdx.x;
    const int strm = blockIdx.y;
    const int tid = threadIdx.x;
    const float* x = (strm == 0) ? h : g;
    const float* ao = AO + (size_t)strm*ROWS*DMODEL + (size_t)row*DMODEL;
    const float* xr = x + (size_t)row*DMODEL;

    float4 a4 = *(const float4*)&ao[tid*4];
    float4 x4 = *(const float4*)&xr[tid*4];
    float y[4] = { a4.x + x4.x, a4.y + x4.y, a4.z + x4.z, a4.w + x4.w };

    float s1 = y[0] + y[1] + y[2] + y[3];
    float s2 = y[0]*y[0] + y[1]*y[1] + y[2]*y[2] + y[3]*y[3];
    #pragma unroll
    for (int off = 16; off > 0; off >>= 1) {
        s1 += __shfl_xor_sync(0xffffffffu, s1, off);
        s2 += __shfl_xor_sync(0xffffffffu, s2, off);
    }
    __shared__ float red[18];
    int warp = tid >> 5, lane = tid & 31;
    if (lane == 0) { red[warp*2] = s1; red[warp*2 + 1] = s2; }
    __syncthreads();
    if (tid == 0) {
        float t1 = 0.f, t2 = 0.f;
        #pragma unroll
        for (int w = 0; w < 8; w++) { t1 += red[w*2]; t2 += red[w*2 + 1]; }
        float mu = t1 * (1.f/DMODEL);
        float var = t2 * (1.f/DMODEL) - mu*mu;
        red[16] = mu;
        red[17] = rsqrtf(var + LN_EPS);
    }
    __syncthreads();
    float mu = red[16], inv = red[17];

    float4 g4 = *(const float4*)&gamma[tid*4];
    float4 b4 = *(const float4*)&beta[tid*4];
    float4 o;
    o.x = g4.x*(y[0] - mu)*inv + b4.x;
    o.y = g4.y*(y[1] - mu)*inv + b4.y;
    o.z = g4.z*(y[2] - mu)*inv + b4.z;
    o.w = g4.w*(y[3] - mu)*inv + b4.w;
    *(float4*)&out[(size_t)strm*ROWS*DMODEL + (size_t)row*DMODEL + tid*4] = o;
}

// ---------------- launch ----------------
extern "C" void kernel_launch(void* const* d_in, const int* in_sizes, int n_in,
                              void* d_out, int out_size) {
    const float* h     = (const float*)d_in[0];
    const float* g     = (const float*)d_in[1];
    const float* Wq    = (const float*)d_in[2];
    const float* Wk    = (const float*)d_in[3];
    const float* Wv    = (const float*)d_in[4];
    const float* Wo    = (const float*)d_in[5];
    const float* rwb   = (const float*)d_in[6];
    const float* gamma = (const float*)d_in[7];
    const float* beta  = (const float*)d_in[8];
    float* out = (float*)d_out;

    float *pAO;
    __nv_bfloat16 *pKb, *pVb, *pQb, *pAVb, *phb, *pgb, *pWqTb, *pWkTb, *pWvTb, *pWob;
    cudaGetSymbolAddress((void**)&pKb,   g_Kb);
    cudaGetSymbolAddress((void**)&pVb,   g_Vb);
    cudaGetSymbolAddress((void**)&pQb,   g_Qb);
    cudaGetSymbolAddress((void**)&pAO,   g_AO);
    cudaGetSymbolAddress((void**)&pAVb,  g_AVb);
    cudaGetSymbolAddress((void**)&phb,   g_hb);
    cudaGetSymbolAddress((void**)&pgb,   g_gb);
    cudaGetSymbolAddress((void**)&pWqTb, g_WqTb);
    cudaGetSymbolAddress((void**)&pWkTb, g_WkTb);
    cudaGetSymbolAddress((void**)&pWvTb, g_WvTb);
    cudaGetSymbolAddress((void**)&pWob,  g_Wob);

    cudaFuncSetAttribute(bgemm, cudaFuncAttributeMaxDynamicSharedMemorySize, BSMEM);
    cudaFuncSetAttribute(flash_bf, cudaFuncAttributeMaxDynamicSharedMemorySize, FBSMEM);

    conv_f2b<<<ROWS*DMODEL/1024, 256>>>(h, phb);
    conv_f2b<<<ROWS*DMODEL/1024, 256>>>(g, pgb);
    conv_f2b<<<DMODEL*DMODEL/1024, 256>>>(Wo, pWob);
    transposeb<<<dim3(32, 32), dim3(32, 8)>>>(Wq, pWqTb);
    transposeb<<<dim3(32, 32), dim3(32, 8)>>>(Wk, pWkTb);
    transposeb<<<dim3(32, 32), dim3(32, 8)>>>(Wv, pWvTb);

    dim3 ggrid(8, 32);
    bgemm<<<ggrid, 256, BSMEM>>>(phb, pWkTb, nullptr, pKb, nullptr, 3);
    bgemm<<<ggrid, 256, BSMEM>>>(phb, pWvTb, nullptr, pVb, nullptr, 3);
    bgemm<<<ggrid, 256, BSMEM>>>(phb, pWqTb, nullptr, pQb, rwb, 4);
    bgemm<<<ggrid, 256, BSMEM>>>(pgb, pWqTb, nullptr, pQb + (size_t)BATCH*NHEAD*SEQ*DHEAD, rwb, 4);

    flash_bf<<<dim3(SEQ/128, BATCH*NHEAD, 2), 256, FBSMEM>>>(pQb, pKb, pVb, pAVb);

    bgemm<<<ggrid, 256, BSMEM>>>(pAVb, pWob, pAO, nullptr, nullptr, 0);
    bgemm<<<ggrid, 256, BSMEM>>>(pAVb + (size_t)ROWS*DMODEL, pWob, pAO + (size_t)ROWS*DMODEL, nullptr, nullptr, 0);

    resid_ln<<<dim3(ROWS, 2), 256>>>(pAO, h, g, gamma, beta, out);
}

// round 7
// speedup vs baseline: 5.6619x; 1.0160x over previous
#include <cuda_runtime.h>
#include <cuda_bf16.h>
#include <cstdint>
#include <math.h>

#define SEQ 2048
#define BATCH 2
#define NHEAD 16
#define DHEAD 64
#define DMODEL 1024
#define ROWS (SEQ*BATCH)          // 4096
#define HEADSZ (BATCH*NHEAD*SEQ*DHEAD)
#define LN_EPS 1e-5f

// ---------------- scratch (static device globals; no allocation) ----------------
__device__ __align__(16) __nv_bfloat16 g_KVb[2*HEADSZ];              // K then V, [b][n][j][d]
__device__ __align__(16) __nv_bfloat16 g_Qb[2*HEADSZ];               // [s][b][n][i][d]
__device__ __align__(16) float g_AO[2*ROWS*DMODEL];                  // attn_out pre-LN
__device__ __align__(16) __nv_bfloat16 g_AVb[2*ROWS*DMODEL];         // attn_vec bf16 (both streams)
__device__ __align__(16) __nv_bfloat16 g_hgb[2*ROWS*DMODEL];         // [h;g] bf16 stacked
__device__ __align__(16) __nv_bfloat16 g_WqTb[DMODEL*DMODEL];        // [n][k]
__device__ __align__(16) __nv_bfloat16 g_WkvT[2*DMODEL*DMODEL];      // [WkT;WvT] stacked on N
__device__ __align__(16) __nv_bfloat16 g_Wob[DMODEL*DMODEL];

// ================= PTX helpers (base sm_103 target only) =================
__device__ __forceinline__ uint32_t s2u(const void* p) {
    uint32_t a;
    asm("{ .reg .u64 t; cvta.to.shared.u64 t, %1; cvt.u32.u64 %0, t; }" : "=r"(a) : "l"(p));
    return a;
}
#define CP_ASYNC16(dst, src) asm volatile("cp.async.cg.shared.global [%0], [%1], 16;" :: "r"(dst), "l"(src))
#define CP_COMMIT()  asm volatile("cp.async.commit_group;")
#define CP_WAIT2()   asm volatile("cp.async.wait_group 2;" ::: "memory")
#define CP_WAIT1()   asm volatile("cp.async.wait_group 1;" ::: "memory")
#define CP_WAIT0()   asm volatile("cp.async.wait_group 0;" ::: "memory")

__device__ __forceinline__ void mma_bf16(float* d, const uint32_t* a, uint32_t b0, uint32_t b1) {
    asm volatile("mma.sync.aligned.m16n8k16.row.col.f32.bf16.bf16.f32 "
        "{%0,%1,%2,%3},{%4,%5,%6,%7},{%8,%9},{%0,%1,%2,%3};"
        : "+f"(d[0]), "+f"(d[1]), "+f"(d[2]), "+f"(d[3])
        : "r"(a[0]), "r"(a[1]), "r"(a[2]), "r"(a[3]), "r"(b0), "r"(b1));
}
__device__ __forceinline__ void ldsm4(uint32_t* r, uint32_t addr) {
    asm volatile("ldmatrix.sync.aligned.m8n8.x4.shared.b16 {%0,%1,%2,%3}, [%4];"
        : "=r"(r[0]), "=r"(r[1]), "=r"(r[2]), "=r"(r[3]) : "r"(addr));
}
__device__ __forceinline__ void ldsm4t(uint32_t* r, uint32_t addr) {
    asm volatile("ldmatrix.sync.aligned.m8n8.x4.trans.shared.b16 {%0,%1,%2,%3}, [%4];"
        : "=r"(r[0]), "=r"(r[1]), "=r"(r[2]), "=r"(r[3]) : "r"(addr));
}
__device__ __forceinline__ uint32_t packbf(float lo, float hi) {
    __nv_bfloat162 t = __floats2bfloat162_rn(lo, hi);
    return *(uint32_t*)&t;
}

// ---------------- fp32 -> bf16: h and g into one stacked buffer ----------------
__global__ void conv_hg(const float* __restrict__ h, const float* __restrict__ g,
                        __nv_bfloat16* __restrict__ out) {
    const float* src = blockIdx.y ? g : h;
    __nv_bfloat16* dst = out + (size_t)blockIdx.y*ROWS*DMODEL;
    int i = (blockIdx.x*blockDim.x + threadIdx.x)*4;
    float4 v = *(const float4*)&src[i];
    *(__nv_bfloat162*)&dst[i]   = __floats2bfloat162_rn(v.x, v.y);
    *(__nv_bfloat162*)&dst[i+2] = __floats2bfloat162_rn(v.z, v.w);
}
__global__ void conv_f2b(const float* __restrict__ in, __nv_bfloat16* __restrict__ out) {
    int i = (blockIdx.x*blockDim.x + threadIdx.x)*4;
    float4 v = *(const float4*)&in[i];
    *(__nv_bfloat162*)&out[i]   = __floats2bfloat162_rn(v.x, v.y);
    *(__nv_bfloat162*)&out[i+2] = __floats2bfloat162_rn(v.z, v.w);
}

// ---------------- transpose+convert: out[n][k] = bf16(in[k][n]) ----------------
__global__ void transposeb(const float* __restrict__ in, __nv_bfloat16* __restrict__ out) {
    __shared__ float t[32][33];
    int x = blockIdx.x*32 + threadIdx.x;
    int y = blockIdx.y*32 + threadIdx.y;
    #pragma unroll
    for (int i = 0; i < 32; i += 8)
        t[threadIdx.y + i][threadIdx.x] = in[(size_t)(y + i)*DMODEL + x];
    __syncthreads();
    x = blockIdx.y*32 + threadIdx.x;
    y = blockIdx.x*32 + threadIdx.y;
    #pragma unroll
    for (int i = 0; i < 32; i += 8)
        out[(size_t)(y + i)*DMODEL + x] = __float2bfloat16(t[threadIdx.x][threadIdx.y + i]);
}

// ---------------- bf16 mma.sync GEMM, 3-stage cp.async pipeline ----------------
// A [M][1024] bf16 row-major, BT [N][1024] bf16 row-major.
// mode 0: fp32 row-major (dstf), M arbitrary
// mode 5: combined KV: col<1024 -> K half of dstb, else V half (head layout)
// mode 6: stacked-Q: strm = row>>12, head layout + bias[col]
#define BTB  10240                   // bytes per tile buffer (128 rows x 80 B)
#define BSMEM (6*BTB)                // 61440 B: A0..A2, B0..B2

__global__ __launch_bounds__(256, 2)
void bgemm(const __nv_bfloat16* __restrict__ A, const __nv_bfloat16* __restrict__ BT,
           float* __restrict__ dstf, __nv_bfloat16* __restrict__ dstb,
           const float* __restrict__ bias, int mode) {
    extern __shared__ char bsm[];
    const uint32_t sbase = s2u(bsm);

    const int tid  = threadIdx.x;
    const int lane = tid & 31, warp = tid >> 5;
    const int wm = warp & 3, wn = warp >> 2;
    const int br = blockIdx.y, bc = blockIdx.x;

    const __nv_bfloat16* srcA[2]; const __nv_bfloat16* srcB[2]; uint32_t doff[2];
    #pragma unroll
    for (int i = 0; i < 2; i++) {
        int f = tid + 256*i;
        int row = f >> 2, seg = f & 3;
        srcA[i] = A  + (size_t)(br*128 + row)*DMODEL + seg*8;
        srcB[i] = BT + (size_t)(bc*128 + row)*DMODEL + seg*8;
        doff[i] = (uint32_t)(row*80 + seg*16);
    }

    auto load_chunk = [&](int c) {
        int buf = c % 3;
        uint32_t ab = sbase + buf*BTB;
        uint32_t bb = sbase + 3*BTB + buf*BTB;
        int kb = c * 32;
        #pragma unroll
        for (int i = 0; i < 2; i++) {
            CP_ASYNC16(ab + doff[i], (const void*)(srcA[i] + kb));
            CP_ASYNC16(bb + doff[i], (const void*)(srcB[i] + kb));
        }
        CP_COMMIT();
    };

    float d[2][8][4];
    #pragma unroll
    for (int mt = 0; mt < 2; mt++)
        #pragma unroll
        for (int nt = 0; nt < 8; nt++)
            #pragma unroll
            for (int j = 0; j < 4; j++) d[mt][nt][j] = 0.f;

    load_chunk(0);
    load_chunk(1);

    const int lg = lane >> 3, lr = lane & 7;
    const int rsel = (lg & 1)*8 + lr;
    const int csel = (lg >> 1)*8;

    for (int c = 0; c < 32; c++) {
        if (c == 31) { CP_WAIT0(); } else { CP_WAIT1(); }
        __syncthreads();
        if (c + 2 < 32) load_chunk(c + 2);

        int buf = c % 3;
        uint32_t Abase = sbase + buf*BTB;
        uint32_t Bbase = sbase + 3*BTB + buf*BTB;

        #pragma unroll
        for (int ks = 0; ks < 2; ks++) {
            uint32_t af[2][4];
            #pragma unroll
            for (int mt = 0; mt < 2; mt++)
                ldsm4(af[mt], Abase + (uint32_t)((wm*32 + mt*16 + rsel)*80 + (ks*16 + csel)*2));
            uint32_t bf[4][4];
            #pragma unroll
            for (int n2 = 0; n2 < 4; n2++)
                ldsm4(bf[n2], Bbase + (uint32_t)((wn*64 + n2*16 + rsel)*80 + (ks*16 + csel)*2));
            #pragma unroll
            for (int mt = 0; mt < 2; mt++)
                #pragma unroll
                for (int n2 = 0; n2 < 4; n2++) {
                    mma_bf16(d[mt][2*n2],   af[mt], bf[n2][0], bf[n2][2]);
                    mma_bf16(d[mt][2*n2+1], af[mt], bf[n2][1], bf[n2][3]);
                }
        }
    }

    const int r0 = wm*32 + (lane >> 2);
    const int cb = wn*64 + 2*(lane & 3);
    #pragma unroll
    for (int mt = 0; mt < 2; mt++) {
        #pragma unroll
        for (int rh = 0; rh < 2; rh++) {
            int row_g = br*128 + r0 + mt*16 + rh*8;
            #pragma unroll
            for (int nt = 0; nt < 8; nt++) {
                int col_g = bc*128 + cb + nt*8;
                float2 v = make_float2(d[mt][nt][2*rh], d[mt][nt][2*rh + 1]);
                if (mode == 0) {
                    *(float2*)&dstf[(size_t)row_g*DMODEL + col_g] = v;
                } else if (mode == 5) {
                    int region = col_g >> 10;             // 0 = K, 1 = V
                    int c1 = col_g & 1023;
                    int i = row_g >> 1, b = row_g & 1;
                    int nh = c1 >> 6, dd = c1 & 63;
                    *(__nv_bfloat162*)&dstb[(size_t)region*HEADSZ +
                        ((size_t)(b*NHEAD + nh)*SEQ + i)*DHEAD + dd] =
                        __floats2bfloat162_rn(v.x, v.y);
                } else {  // mode 6: stacked Q + bias
                    v.x += bias[col_g];
                    v.y += bias[col_g + 1];
                    int strm = row_g >> 12;
                    int lrow = row_g & 4095;
                    int i = lrow >> 1, b = lrow & 1;
                    int nh = col_g >> 6, dd = col_g & 63;
                    *(__nv_bfloat162*)&dstb[(size_t)strm*HEADSZ +
                        ((size_t)(b*NHEAD + nh)*SEQ + i)*DHEAD + dd] =
                        __floats2bfloat162_rn(v.x, v.y);
                }
            }
        }
    }
}

// ---------------- flash attention, bf16 mma + ldmatrix, 3-stage KV pipeline ----------------
// grid (16, 32, 2), block 256 (8 warps x 16 rows of a 128-row Q tile), BN=64
// smem rows 144 B. Layout: Q [0,18432), KV buf i at 18432 + i*18432 (K 9216 + V 9216)
#define KPB 144
#define FBSMEM (18432*4)   // 73728

__global__ __launch_bounds__(256)
void flash_bf(const __nv_bfloat16* __restrict__ Qall, const __nv_bfloat16* __restrict__ Kg,
              const __nv_bfloat16* __restrict__ Vg, __nv_bfloat16* __restrict__ AVb) {
    extern __shared__ char fs[];
    const uint32_t sb = s2u(fs);
    const int tid = threadIdx.x, lane = tid & 31, warp = tid >> 5;
    const int r = lane >> 2, qd = lane & 3, lg = lane >> 3, lr = lane & 7;
    const int wr = warp*16;
    const int i0 = blockIdx.x*128, bn = blockIdx.y, strm = blockIdx.z;

    const __nv_bfloat16* q  = Qall + ((size_t)(strm*BATCH*NHEAD + bn)*SEQ + i0)*DHEAD;
    const __nv_bfloat16* kp = Kg + (size_t)bn*SEQ*DHEAD;
    const __nv_bfloat16* vp = Vg + (size_t)bn*SEQ*DHEAD;

    // Q stage (group 0)
    #pragma unroll
    for (int i = 0; i < 4; i++) {
        int f = tid + 256*i;
        int row = f >> 3, seg = f & 7;
        CP_ASYNC16(sb + row*KPB + seg*16, (const void*)(q + row*64 + seg*8));
    }
    CP_COMMIT();

    auto load_tile = [&](int jt) {
        int buf = jt % 3, j0 = jt*64;
        uint32_t kb = sb + 18432 + buf*18432;
        uint32_t vb = kb + 9216;
        #pragma unroll
        for (int i = 0; i < 2; i++) {
            int f = tid + 256*i;
            int row = f >> 3, seg = f & 7;
            CP_ASYNC16(kb + row*KPB + seg*16, (const void*)(kp + (size_t)(j0+row)*64 + seg*8));
            CP_ASYNC16(vb + row*KPB + seg*16, (const void*)(vp + (size_t)(j0+row)*64 + seg*8));
        }
        CP_COMMIT();
    };
    load_tile(0);
    load_tile(1);

    CP_WAIT2();              // Q resident
    __syncthreads();
    uint32_t qf[4][4];
    #pragma unroll
    for (int ks = 0; ks < 4; ks++)
        ldsm4(qf[ks], sb + (uint32_t)((wr + (lg&1)*8 + lr)*KPB + (ks*16 + (lg>>1)*8)*2));

    float m0 = -1e30f, m1 = -1e30f, l0 = 0.f, l1 = 0.f;
    float oacc[8][4];
    #pragma unroll
    for (int nt = 0; nt < 8; nt++)
        #pragma unroll
        for (int j = 0; j < 4; j++) oacc[nt][j] = 0.f;

    for (int jt = 0; jt < 32; jt++) {
        if (jt == 31) { CP_WAIT0(); } else { CP_WAIT1(); }
        __syncthreads();
        if (jt + 2 < 32) load_tile(jt + 2);

        int buf = jt % 3;
        uint32_t kb = sb + 18432 + buf*18432;
        uint32_t vb = kb + 9216;

        // S = Q K^T (fp32 accum)
        float sacc[8][4];
        #pragma unroll
        for (int nt = 0; nt < 8; nt++)
            #pragma unroll
            for (int j = 0; j < 4; j++) sacc[nt][j] = 0.f;
        #pragma unroll
        for (int ks = 0; ks < 4; ks++) {
            uint32_t bfk[4][4];
            #pragma unroll
            for (int n2 = 0; n2 < 4; n2++)
                ldsm4(bfk[n2], kb + (uint32_t)((n2*16 + (lg&1)*8 + lr)*KPB + (ks*16 + (lg>>1)*8)*2));
            #pragma unroll
            for (int n2 = 0; n2 < 4; n2++) {
                mma_bf16(sacc[2*n2],   qf[ks], bfk[n2][0], bfk[n2][2]);
                mma_bf16(sacc[2*n2+1], qf[ks], bfk[n2][1], bfk[n2][3]);
            }
        }

        // scale + online softmax
        #pragma unroll
        for (int nt = 0; nt < 8; nt++)
            #pragma unroll
            for (int j = 0; j < 4; j++) sacc[nt][j] *= 0.125f;
        float mx0 = -1e30f, mx1 = -1e30f;
        #pragma unroll
        for (int nt = 0; nt < 8; nt++) {
            mx0 = fmaxf(mx0, fmaxf(sacc[nt][0], sacc[nt][1]));
            mx1 = fmaxf(mx1, fmaxf(sacc[nt][2], sacc[nt][3]));
        }
        mx0 = fmaxf(mx0, __shfl_xor_sync(0xffffffffu, mx0, 1));
        mx0 = fmaxf(mx0, __shfl_xor_sync(0xffffffffu, mx0, 2));
        mx1 = fmaxf(mx1, __shfl_xor_sync(0xffffffffu, mx1, 1));
        mx1 = fmaxf(mx1, __shfl_xor_sync(0xffffffffu, mx1, 2));
        float nm0 = fmaxf(m0, mx0), nm1 = fmaxf(m1, mx1);
        float a0 = __expf(m0 - nm0), a1 = __expf(m1 - nm1);
        float rs0 = 0.f, rs1 = 0.f;
        #pragma unroll
        for (int nt = 0; nt < 8; nt++) {
            sacc[nt][0] = __expf(sacc[nt][0] - nm0);
            sacc[nt][1] = __expf(sacc[nt][1] - nm0);
            sacc[nt][2] = __expf(sacc[nt][2] - nm1);
            sacc[nt][3] = __expf(sacc[nt][3] - nm1);
            rs0 += sacc[nt][0] + sacc[nt][1];
            rs1 += sacc[nt][2] + sacc[nt][3];
        }
        rs0 += __shfl_xor_sync(0xffffffffu, rs0, 1);
        rs0 += __shfl_xor_sync(0xffffffffu, rs0, 2);
        rs1 += __shfl_xor_sync(0xffffffffu, rs1, 1);
        rs1 += __shfl_xor_sync(0xffffffffu, rs1, 2);
        m0 = nm0; m1 = nm1;
        l0 = l0*a0 + rs0; l1 = l1*a1 + rs1;
        #pragma unroll
        for (int nt = 0; nt < 8; nt++) {
            oacc[nt][0] *= a0; oacc[nt][1] *= a0;
            oacc[nt][2] *= a1; oacc[nt][3] *= a1;
        }

        // P fragments straight from registers
        uint32_t paf[4][4];
        #pragma unroll
        for (int kt = 0; kt < 4; kt++) {
            paf[kt][0] = packbf(sacc[2*kt][0],   sacc[2*kt][1]);
            paf[kt][1] = packbf(sacc[2*kt][2],   sacc[2*kt][3]);
            paf[kt][2] = packbf(sacc[2*kt+1][0], sacc[2*kt+1][1]);
            paf[kt][3] = packbf(sacc[2*kt+1][2], sacc[2*kt+1][3]);
        }

        // O += P V (V^T via ldmatrix.trans)
        #pragma unroll
        for (int kt = 0; kt < 4; kt++) {
            uint32_t bfv[4][4];
            #pragma unroll
            for (int n2 = 0; n2 < 4; n2++)
                ldsm4t(bfv[n2], vb + (uint32_t)((kt*16 + (lg>>1)*8 + lr)*KPB + (n2*16 + (lg&1)*8)*2));
            #pragma unroll
            for (int n2 = 0; n2 < 4; n2++) {
                mma_bf16(oacc[2*n2],   paf[kt], bfv[n2][0], bfv[n2][2]);
                mma_bf16(oacc[2*n2+1], paf[kt], bfv[n2][1], bfv[n2][3]);
            }
        }
    }

    // epilogue -> AV bf16 row-major
    const float inv0 = 1.f / l0, inv1 = 1.f / l1;
    const int b = bn >> 4, nh = bn & 15;
    __nv_bfloat16* outp = AVb + (size_t)strm*ROWS*DMODEL;
    const int ir0 = i0 + wr + r, ir1 = ir0 + 8;
    #pragma unroll
    for (int nt = 0; nt < 8; nt++) {
        int col = nh*DHEAD + nt*8 + 2*qd;
        *(__nv_bfloat162*)&outp[(size_t)(ir0*BATCH + b)*DMODEL + col] =
            __floats2bfloat162_rn(oacc[nt][0]*inv0, oacc[nt][1]*inv0);
        *(__nv_bfloat162*)&outp[(size_t)(ir1*BATCH + b)*DMODEL + col] =
            __floats2bfloat162_rn(oacc[nt][2]*inv1, oacc[nt][3]*inv1);
    }
}

// ---------------- residual + layernorm ----------------
__global__ __launch_bounds__(256)
void resid_ln(const float* __restrict__ AO, const float* __restrict__ h,
              const float* __restrict__ g, const float* __restrict__ gamma,
              const float* __restrict__ beta, float* __restrict__ out) {
    const int row = blockIdx.x;
    const int strm = blockIdx.y;
    const int tid = threadIdx.x;
    const float* x = (strm == 0) ? h : g;
    const float* ao = AO + (size_t)strm*ROWS*DMODEL + (size_t)row*DMODEL;
    const float* xr = x + (size_t)row*DMODEL;

    float4 a4 = *(const float4*)&ao[tid*4];
    float4 x4 = *(const float4*)&xr[tid*4];
    float y[4] = { a4.x + x4.x, a4.y + x4.y, a4.z + x4.z, a4.w + x4.w };

    float s1 = y[0] + y[1] + y[2] + y[3];
    float s2 = y[0]*y[0] + y[1]*y[1] + y[2]*y[2] + y[3]*y[3];
    #pragma unroll
    for (int off = 16; off > 0; off >>= 1) {
        s1 += __shfl_xor_sync(0xffffffffu, s1, off);
        s2 += __shfl_xor_sync(0xffffffffu, s2, off);
    }
    __shared__ float red[18];
    int warp = tid >> 5, lane = tid & 31;
    if (lane == 0) { red[warp*2] = s1; red[warp*2 + 1] = s2; }
    __syncthreads();
    if (tid == 0) {
        float t1 = 0.f, t2 = 0.f;
        #pragma unroll
        for (int w = 0; w < 8; w++) { t1 += red[w*2]; t2 += red[w*2 + 1]; }
        float mu = t1 * (1.f/DMODEL);
        float var = t2 * (1.f/DMODEL) - mu*mu;
        red[16] = mu;
        red[17] = rsqrtf(var + LN_EPS);
    }
    __syncthreads();
    float mu = red[16], inv = red[17];

    float4 g4 = *(const float4*)&gamma[tid*4];
    float4 b4 = *(const float4*)&beta[tid*4];
    float4 o;
    o.x = g4.x*(y[0] - mu)*inv + b4.x;
    o.y = g4.y*(y[1] - mu)*inv + b4.y;
    o.z = g4.z*(y[2] - mu)*inv + b4.z;
    o.w = g4.w*(y[3] - mu)*inv + b4.w;
    *(float4*)&out[(size_t)strm*ROWS*DMODEL + (size_t)row*DMODEL + tid*4] = o;
}

// ---------------- launch ----------------
extern "C" void kernel_launch(void* const* d_in, const int* in_sizes, int n_in,
                              void* d_out, int out_size) {
    const float* h     = (const float*)d_in[0];
    const float* g     = (const float*)d_in[1];
    const float* Wq    = (const float*)d_in[2];
    const float* Wk    = (const float*)d_in[3];
    const float* Wv    = (const float*)d_in[4];
    const float* Wo    = (const float*)d_in[5];
    const float* rwb   = (const float*)d_in[6];
    const float* gamma = (const float*)d_in[7];
    const float* beta  = (const float*)d_in[8];
    float* out = (float*)d_out;

    float *pAO;
    __nv_bfloat16 *pKVb, *pQb, *pAVb, *phgb, *pWqTb, *pWkvT, *pWob;
    cudaGetSymbolAddress((void**)&pKVb,  g_KVb);
    cudaGetSymbolAddress((void**)&pQb,   g_Qb);
    cudaGetSymbolAddress((void**)&pAO,   g_AO);
    cudaGetSymbolAddress((void**)&pAVb,  g_AVb);
    cudaGetSymbolAddress((void**)&phgb,  g_hgb);
    cudaGetSymbolAddress((void**)&pWqTb, g_WqTb);
    cudaGetSymbolAddress((void**)&pWkvT, g_WkvT);
    cudaGetSymbolAddress((void**)&pWob,  g_Wob);

    cudaFuncSetAttribute(bgemm, cudaFuncAttributeMaxDynamicSharedMemorySize, BSMEM);
    cudaFuncSetAttribute(flash_bf, cudaFuncAttributeMaxDynamicSharedMemorySize, FBSMEM);

    conv_hg<<<dim3(ROWS*DMODEL/1024, 2), 256>>>(h, g, phgb);
    conv_f2b<<<DMODEL*DMODEL/1024, 256>>>(Wo, pWob);
    transposeb<<<dim3(32, 32), dim3(32, 8)>>>(Wq, pWqTb);
    transposeb<<<dim3(32, 32), dim3(32, 8)>>>(Wk, pWkvT);
    transposeb<<<dim3(32, 32), dim3(32, 8)>>>(Wv, pWkvT + (size_t)DMODEL*DMODEL);

    // (1) K+V projections: A = h (first half of hgb), BT = [WkT;WvT], N=2048
    bgemm<<<dim3(16, 32), 256, BSMEM>>>(phgb, pWkvT, nullptr, pKVb, nullptr, 5);
    // (2) Q projections, both streams: A = [h;g] (M=8192), BT = WqT
    bgemm<<<dim3(8, 64), 256, BSMEM>>>(phgb, pWqTb, nullptr, pQb, rwb, 6);

    flash_bf<<<dim3(SEQ/128, BATCH*NHEAD, 2), 256, FBSMEM>>>(pQb, pKVb, pKVb + HEADSZ, pAVb);

    // (3) output projection, both streams: A = AV (M=8192), BT = Wo
    bgemm<<<dim3(8, 64), 256, BSMEM>>>(pAVb, pWob, pAO, nullptr, nullptr, 0);

    resid_ln<<<dim3(ROWS, 2), 256>>>(pAO, h, g, gamma, beta, out);
}

// round 8
// speedup vs baseline: 6.1185x; 1.0807x over previous
#include <cuda_runtime.h>
#include <cuda_bf16.h>
#include <cstdint>
#include <math.h>

#define SEQ 2048
#define BATCH 2
#define NHEAD 16
#define DHEAD 64
#define DMODEL 1024
#define ROWS (SEQ*BATCH)          // 4096
#define HEADSZ (BATCH*NHEAD*SEQ*DHEAD)
#define LN_EPS 1e-5f

// ---------------- scratch (static device globals; no allocation) ----------------
__device__ __align__(16) __nv_bfloat16 g_KVb[2*HEADSZ];              // K then V, [b][n][j][d]
__device__ __align__(16) __nv_bfloat16 g_Qb[2*HEADSZ];               // [s][b][n][i][d]
__device__ __align__(16) float g_AO[2*ROWS*DMODEL];                  // attn_out pre-LN
__device__ __align__(16) __nv_bfloat16 g_AVb[2*ROWS*DMODEL];         // attn_vec bf16
__device__ __align__(16) __nv_bfloat16 g_hgb[2*ROWS*DMODEL];         // [h;g] bf16 stacked
__device__ __align__(16) __nv_bfloat16 g_WqTb[DMODEL*DMODEL];        // [n][k]
__device__ __align__(16) __nv_bfloat16 g_WkvT[2*DMODEL*DMODEL];      // [WkT;WvT]
__device__ __align__(16) __nv_bfloat16 g_Wob[DMODEL*DMODEL];

// ================= PTX helpers (base sm_103 target only) =================
__device__ __forceinline__ uint32_t s2u(const void* p) {
    uint32_t a;
    asm("{ .reg .u64 t; cvta.to.shared.u64 t, %1; cvt.u32.u64 %0, t; }" : "=r"(a) : "l"(p));
    return a;
}
#define CP_ASYNC16(dst, src) asm volatile("cp.async.cg.shared.global [%0], [%1], 16;" :: "r"(dst), "l"(src))
#define CP_COMMIT()  asm volatile("cp.async.commit_group;")
#define CP_WAIT2()   asm volatile("cp.async.wait_group 2;" ::: "memory")
#define CP_WAIT1()   asm volatile("cp.async.wait_group 1;" ::: "memory")
#define CP_WAIT0()   asm volatile("cp.async.wait_group 0;" ::: "memory")

__device__ __forceinline__ void mma_bf16(float* d, const uint32_t* a, uint32_t b0, uint32_t b1) {
    asm volatile("mma.sync.aligned.m16n8k16.row.col.f32.bf16.bf16.f32 "
        "{%0,%1,%2,%3},{%4,%5,%6,%7},{%8,%9},{%0,%1,%2,%3};"
        : "+f"(d[0]), "+f"(d[1]), "+f"(d[2]), "+f"(d[3])
        : "r"(a[0]), "r"(a[1]), "r"(a[2]), "r"(a[3]), "r"(b0), "r"(b1));
}
__device__ __forceinline__ void ldsm4(uint32_t* r, uint32_t addr) {
    asm volatile("ldmatrix.sync.aligned.m8n8.x4.shared.b16 {%0,%1,%2,%3}, [%4];"
        : "=r"(r[0]), "=r"(r[1]), "=r"(r[2]), "=r"(r[3]) : "r"(addr));
}
__device__ __forceinline__ void ldsm4t(uint32_t* r, uint32_t addr) {
    asm volatile("ldmatrix.sync.aligned.m8n8.x4.trans.shared.b16 {%0,%1,%2,%3}, [%4];"
        : "=r"(r[0]), "=r"(r[1]), "=r"(r[2]), "=r"(r[3]) : "r"(addr));
}
__device__ __forceinline__ uint32_t packbf(float lo, float hi) {
    __nv_bfloat162 t = __floats2bfloat162_rn(lo, hi);
    return *(uint32_t*)&t;
}

// ---------------- fp32 -> bf16: h and g into one stacked buffer ----------------
__global__ void conv_hg(const float* __restrict__ h, const float* __restrict__ g,
                        __nv_bfloat16* __restrict__ out) {
    const float* src = blockIdx.y ? g : h;
    __nv_bfloat16* dst = out + (size_t)blockIdx.y*ROWS*DMODEL;
    int i = (blockIdx.x*blockDim.x + threadIdx.x)*4;
    float4 v = *(const float4*)&src[i];
    *(__nv_bfloat162*)&dst[i]   = __floats2bfloat162_rn(v.x, v.y);
    *(__nv_bfloat162*)&dst[i+2] = __floats2bfloat162_rn(v.z, v.w);
}
__global__ void conv_f2b(const float* __restrict__ in, __nv_bfloat16* __restrict__ out) {
    int i = (blockIdx.x*blockDim.x + threadIdx.x)*4;
    float4 v = *(const float4*)&in[i];
    *(__nv_bfloat162*)&out[i]   = __floats2bfloat162_rn(v.x, v.y);
    *(__nv_bfloat162*)&out[i+2] = __floats2bfloat162_rn(v.z, v.w);
}

// ---------------- 3-way transpose+convert: out[n][k] = bf16(in[k][n]) ----------------
__global__ void transposeb3(const float* __restrict__ Wq, const float* __restrict__ Wk,
                            const float* __restrict__ Wv,
                            __nv_bfloat16* __restrict__ oQ, __nv_bfloat16* __restrict__ oKV) {
    __shared__ float t[32][33];
    const float* in = (blockIdx.z == 0) ? Wq : (blockIdx.z == 1 ? Wk : Wv);
    __nv_bfloat16* out = (blockIdx.z == 0) ? oQ : oKV + (size_t)(blockIdx.z - 1)*DMODEL*DMODEL;
    int x = blockIdx.x*32 + threadIdx.x;
    int y = blockIdx.y*32 + threadIdx.y;
    #pragma unroll
    for (int i = 0; i < 32; i += 8)
        t[threadIdx.y + i][threadIdx.x] = in[(size_t)(y + i)*DMODEL + x];
    __syncthreads();
    x = blockIdx.y*32 + threadIdx.x;
    y = blockIdx.x*32 + threadIdx.y;
    #pragma unroll
    for (int i = 0; i < 32; i += 8)
        out[(size_t)(y + i)*DMODEL + x] = __float2bfloat16(t[threadIdx.x][threadIdx.y + i]);
}

// ---------------- bf16 mma.sync GEMM, K-chunk 64, 3-stage pipeline ----------------
// A [M][1024] bf16 row-major, BT [N][1024] bf16 row-major.
// Row pitch 144 B in smem (conflict-free for ldmatrix & cp.async).
// mode 0: fp32 row-major; mode 5: combined KV head layout; mode 6: stacked-Q + bias
#define BTB  18432                   // 128 rows x 144 B
#define BSMEM (6*BTB)                // 110592 B: A0..A2, B0..B2

__global__ __launch_bounds__(256, 2)
void bgemm(const __nv_bfloat16* __restrict__ A, const __nv_bfloat16* __restrict__ BT,
           float* __restrict__ dstf, __nv_bfloat16* __restrict__ dstb,
           const float* __restrict__ bias, int mode) {
    extern __shared__ char bsm[];
    const uint32_t sbase = s2u(bsm);

    const int tid  = threadIdx.x;
    const int lane = tid & 31, warp = tid >> 5;
    const int wm = warp & 3, wn = warp >> 2;
    const int br = blockIdx.y, bc = blockIdx.x;

    // base load slot: row = tid>>3 (+32 per pass), seg = tid&7 (16B)
    const int lrow = tid >> 3, lseg = tid & 7;
    const __nv_bfloat16* srcA0 = A  + (size_t)(br*128 + lrow)*DMODEL + lseg*8;
    const __nv_bfloat16* srcB0 = BT + (size_t)(bc*128 + lrow)*DMODEL + lseg*8;
    const uint32_t doff0 = (uint32_t)(lrow*144 + lseg*16);

    auto load_chunk = [&](int c) {
        int buf = c % 3;
        uint32_t ab = sbase + buf*BTB;
        uint32_t bb = sbase + 3*BTB + buf*BTB;
        int kb = c * 64;
        #pragma unroll
        for (int i = 0; i < 4; i++) {
            CP_ASYNC16(ab + doff0 + i*32*144, (const void*)(srcA0 + kb + (size_t)i*32*DMODEL));
            CP_ASYNC16(bb + doff0 + i*32*144, (const void*)(srcB0 + kb + (size_t)i*32*DMODEL));
        }
        CP_COMMIT();
    };

    float d[2][8][4];
    #pragma unroll
    for (int mt = 0; mt < 2; mt++)
        #pragma unroll
        for (int nt = 0; nt < 8; nt++)
            #pragma unroll
            for (int j = 0; j < 4; j++) d[mt][nt][j] = 0.f;

    load_chunk(0);
    load_chunk(1);

    const int lg = lane >> 3, lr = lane & 7;
    const int rsel = (lg & 1)*8 + lr;
    const int csel = (lg >> 1)*8;

    for (int c = 0; c < 16; c++) {
        if (c == 15) { CP_WAIT0(); } else { CP_WAIT1(); }
        __syncthreads();
        if (c + 2 < 16) load_chunk(c + 2);

        int buf = c % 3;
        uint32_t Abase = sbase + buf*BTB;
        uint32_t Bbase = sbase + 3*BTB + buf*BTB;

        #pragma unroll
        for (int ks = 0; ks < 4; ks++) {
            uint32_t af[2][4];
            #pragma unroll
            for (int mt = 0; mt < 2; mt++)
                ldsm4(af[mt], Abase + (uint32_t)((wm*32 + mt*16 + rsel)*144 + (ks*16 + csel)*2));
            uint32_t bf[4][4];
            #pragma unroll
            for (int n2 = 0; n2 < 4; n2++)
                ldsm4(bf[n2], Bbase + (uint32_t)((wn*64 + n2*16 + rsel)*144 + (ks*16 + csel)*2));
            #pragma unroll
            for (int mt = 0; mt < 2; mt++)
                #pragma unroll
                for (int n2 = 0; n2 < 4; n2++) {
                    mma_bf16(d[mt][2*n2],   af[mt], bf[n2][0], bf[n2][2]);
                    mma_bf16(d[mt][2*n2+1], af[mt], bf[n2][1], bf[n2][3]);
                }
        }
    }

    const int r0 = wm*32 + (lane >> 2);
    const int cb = wn*64 + 2*(lane & 3);
    #pragma unroll
    for (int mt = 0; mt < 2; mt++) {
        #pragma unroll
        for (int rh = 0; rh < 2; rh++) {
            int row_g = br*128 + r0 + mt*16 + rh*8;
            #pragma unroll
            for (int nt = 0; nt < 8; nt++) {
                int col_g = bc*128 + cb + nt*8;
                float2 v = make_float2(d[mt][nt][2*rh], d[mt][nt][2*rh + 1]);
                if (mode == 0) {
                    *(float2*)&dstf[(size_t)row_g*DMODEL + col_g] = v;
                } else if (mode == 5) {
                    int region = col_g >> 10;             // 0 = K, 1 = V
                    int c1 = col_g & 1023;
                    int i = row_g >> 1, b = row_g & 1;
                    int nh = c1 >> 6, dd = c1 & 63;
                    *(__nv_bfloat162*)&dstb[(size_t)region*HEADSZ +
                        ((size_t)(b*NHEAD + nh)*SEQ + i)*DHEAD + dd] =
                        __floats2bfloat162_rn(v.x, v.y);
                } else {  // mode 6: stacked Q + bias
                    v.x += bias[col_g];
                    v.y += bias[col_g + 1];
                    int strm = row_g >> 12;
                    int lrow2 = row_g & 4095;
                    int i = lrow2 >> 1, b = lrow2 & 1;
                    int nh = col_g >> 6, dd = col_g & 63;
                    *(__nv_bfloat162*)&dstb[(size_t)strm*HEADSZ +
                        ((size_t)(b*NHEAD + nh)*SEQ + i)*DHEAD + dd] =
                        __floats2bfloat162_rn(v.x, v.y);
                }
            }
        }
    }
}

// ---------------- flash attention, bf16 mma + ldmatrix, 3-stage KV pipeline ----------------
// grid (16, 32, 2), block 256 (8 warps x 16 rows of a 128-row Q tile), BN=64, 2 CTA/SM
#define KPB 144
#define FBSMEM (18432*4)   // 73728

__global__ __launch_bounds__(256, 2)
void flash_bf(const __nv_bfloat16* __restrict__ Qall, const __nv_bfloat16* __restrict__ Kg,
              const __nv_bfloat16* __restrict__ Vg, __nv_bfloat16* __restrict__ AVb) {
    extern __shared__ char fs[];
    const uint32_t sb = s2u(fs);
    const int tid = threadIdx.x, lane = tid & 31, warp = tid >> 5;
    const int r = lane >> 2, qd = lane & 3, lg = lane >> 3, lr = lane & 7;
    const int wr = warp*16;
    const int i0 = blockIdx.x*128, bn = blockIdx.y, strm = blockIdx.z;

    const __nv_bfloat16* q  = Qall + ((size_t)(strm*BATCH*NHEAD + bn)*SEQ + i0)*DHEAD;
    const __nv_bfloat16* kp = Kg + (size_t)bn*SEQ*DHEAD;
    const __nv_bfloat16* vp = Vg + (size_t)bn*SEQ*DHEAD;

    // Q stage (group 0)
    #pragma unroll
    for (int i = 0; i < 4; i++) {
        int f = tid + 256*i;
        int row = f >> 3, seg = f & 7;
        CP_ASYNC16(sb + row*KPB + seg*16, (const void*)(q + row*64 + seg*8));
    }
    CP_COMMIT();

    auto load_tile = [&](int jt) {
        int buf = jt % 3, j0 = jt*64;
        uint32_t kb = sb + 18432 + buf*18432;
        uint32_t vb = kb + 9216;
        #pragma unroll
        for (int i = 0; i < 2; i++) {
            int f = tid + 256*i;
            int row = f >> 3, seg = f & 7;
            CP_ASYNC16(kb + row*KPB + seg*16, (const void*)(kp + (size_t)(j0+row)*64 + seg*8));
            CP_ASYNC16(vb + row*KPB + seg*16, (const void*)(vp + (size_t)(j0+row)*64 + seg*8));
        }
        CP_COMMIT();
    };
    load_tile(0);
    load_tile(1);

    CP_WAIT2();              // Q resident
    __syncthreads();
    uint32_t qf[4][4];
    #pragma unroll
    for (int ks = 0; ks < 4; ks++)
        ldsm4(qf[ks], sb + (uint32_t)((wr + (lg&1)*8 + lr)*KPB + (ks*16 + (lg>>1)*8)*2));

    float m0 = -1e30f, m1 = -1e30f, l0 = 0.f, l1 = 0.f;
    float oacc[8][4];
    #pragma unroll
    for (int nt = 0; nt < 8; nt++)
        #pragma unroll
        for (int j = 0; j < 4; j++) oacc[nt][j] = 0.f;

    for (int jt = 0; jt < 32; jt++) {
        if (jt == 31) { CP_WAIT0(); } else { CP_WAIT1(); }
        __syncthreads();
        if (jt + 2 < 32) load_tile(jt + 2);

        int buf = jt % 3;
        uint32_t kb = sb + 18432 + buf*18432;
        uint32_t vb = kb + 9216;

        // S = Q K^T (fp32 accum)
        float sacc[8][4];
        #pragma unroll
        for (int nt = 0; nt < 8; nt++)
            #pragma unroll
            for (int j = 0; j < 4; j++) sacc[nt][j] = 0.f;
        #pragma unroll
        for (int ks = 0; ks < 4; ks++) {
            uint32_t bfk[4][4];
            #pragma unroll
            for (int n2 = 0; n2 < 4; n2++)
                ldsm4(bfk[n2], kb + (uint32_t)((n2*16 + (lg&1)*8 + lr)*KPB + (ks*16 + (lg>>1)*8)*2));
            #pragma unroll
            for (int n2 = 0; n2 < 4; n2++) {
                mma_bf16(sacc[2*n2],   qf[ks], bfk[n2][0], bfk[n2][2]);
                mma_bf16(sacc[2*n2+1], qf[ks], bfk[n2][1], bfk[n2][3]);
            }
        }

        // scale + online softmax
        #pragma unroll
        for (int nt = 0; nt < 8; nt++)
            #pragma unroll
            for (int j = 0; j < 4; j++) sacc[nt][j] *= 0.125f;
        float mx0 = -1e30f, mx1 = -1e30f;
        #pragma unroll
        for (int nt = 0; nt < 8; nt++) {
            mx0 = fmaxf(mx0, fmaxf(sacc[nt][0], sacc[nt][1]));
            mx1 = fmaxf(mx1, fmaxf(sacc[nt][2], sacc[nt][3]));
        }
        mx0 = fmaxf(mx0, __shfl_xor_sync(0xffffffffu, mx0, 1));
        mx0 = fmaxf(mx0, __shfl_xor_sync(0xffffffffu, mx0, 2));
        mx1 = fmaxf(mx1, __shfl_xor_sync(0xffffffffu, mx1, 1));
        mx1 = fmaxf(mx1, __shfl_xor_sync(0xffffffffu, mx1, 2));
        float nm0 = fmaxf(m0, mx0), nm1 = fmaxf(m1, mx1);
        float a0 = __expf(m0 - nm0), a1 = __expf(m1 - nm1);
        float rs0 = 0.f, rs1 = 0.f;
        #pragma unroll
        for (int nt = 0; nt < 8; nt++) {
            sacc[nt][0] = __expf(sacc[nt][0] - nm0);
            sacc[nt][1] = __expf(sacc[nt][1] - nm0);
            sacc[nt][2] = __expf(sacc[nt][2] - nm1);
            sacc[nt][3] = __expf(sacc[nt][3] - nm1);
            rs0 += sacc[nt][0] + sacc[nt][1];
            rs1 += sacc[nt][2] + sacc[nt][3];
        }
        rs0 += __shfl_xor_sync(0xffffffffu, rs0, 1);
        rs0 += __shfl_xor_sync(0xffffffffu, rs0, 2);
        rs1 += __shfl_xor_sync(0xffffffffu, rs1, 1);
        rs1 += __shfl_xor_sync(0xffffffffu, rs1, 2);
        m0 = nm0; m1 = nm1;
        l0 = l0*a0 + rs0; l1 = l1*a1 + rs1;
        #pragma unroll
        for (int nt = 0; nt < 8; nt++) {
            oacc[nt][0] *= a0; oacc[nt][1] *= a0;
            oacc[nt][2] *= a1; oacc[nt][3] *= a1;
        }

        // P fragments straight from registers
        uint32_t paf[4][4];
        #pragma unroll
        for (int kt = 0; kt < 4; kt++) {
            paf[kt][0] = packbf(sacc[2*kt][0],   sacc[2*kt][1]);
            paf[kt][1] = packbf(sacc[2*kt][2],   sacc[2*kt][3]);
            paf[kt][2] = packbf(sacc[2*kt+1][0], sacc[2*kt+1][1]);
            paf[kt][3] = packbf(sacc[2*kt+1][2], sacc[2*kt+1][3]);
        }

        // O += P V (V^T via ldmatrix.trans)
        #pragma unroll
        for (int kt = 0; kt < 4; kt++) {
            uint32_t bfv[4][4];
            #pragma unroll
            for (int n2 = 0; n2 < 4; n2++)
                ldsm4t(bfv[n2], vb + (uint32_t)((kt*16 + (lg>>1)*8 + lr)*KPB + (n2*16 + (lg&1)*8)*2));
            #pragma unroll
            for (int n2 = 0; n2 < 4; n2++) {
                mma_bf16(oacc[2*n2],   paf[kt], bfv[n2][0], bfv[n2][2]);
                mma_bf16(oacc[2*n2+1], paf[kt], bfv[n2][1], bfv[n2][3]);
            }
        }
    }

    // epilogue -> AV bf16 row-major
    const float inv0 = 1.f / l0, inv1 = 1.f / l1;
    const int b = bn >> 4, nh = bn & 15;
    __nv_bfloat16* outp = AVb + (size_t)strm*ROWS*DMODEL;
    const int ir0 = i0 + wr + r, ir1 = ir0 + 8;
    #pragma unroll
    for (int nt = 0; nt < 8; nt++) {
        int col = nh*DHEAD + nt*8 + 2*qd;
        *(__nv_bfloat162*)&outp[(size_t)(ir0*BATCH + b)*DMODEL + col] =
            __floats2bfloat162_rn(oacc[nt][0]*inv0, oacc[nt][1]*inv0);
        *(__nv_bfloat162*)&outp[(size_t)(ir1*BATCH + b)*DMODEL + col] =
            __floats2bfloat162_rn(oacc[nt][2]*inv1, oacc[nt][3]*inv1);
    }
}

// ---------------- residual + layernorm ----------------
__global__ __launch_bounds__(256)
void resid_ln(const float* __restrict__ AO, const float* __restrict__ h,
              const float* __restrict__ g, const float* __restrict__ gamma,
              const float* __restrict__ beta, float* __restrict__ out) {
    const int row = blockIdx.x;
    const int strm = blockIdx.y;
    const int tid = threadIdx.x;
    const float* x = (strm == 0) ? h : g;
    const float* ao = AO + (size_t)strm*ROWS*DMODEL + (size_t)row*DMODEL;
    const float* xr = x + (size_t)row*DMODEL;

    float4 a4 = *(const float4*)&ao[tid*4];
    float4 x4 = *(const float4*)&xr[tid*4];
    float y[4] = { a4.x + x4.x, a4.y + x4.y, a4.z + x4.z, a4.w + x4.w };

    float s1 = y[0] + y[1] + y[2] + y[3];
    float s2 = y[0]*y[0] + y[1]*y[1] + y[2]*y[2] + y[3]*y[3];
    #pragma unroll
    for (int off = 16; off > 0; off >>= 1) {
        s1 += __shfl_xor_sync(0xffffffffu, s1, off);
        s2 += __shfl_xor_sync(0xffffffffu, s2, off);
    }
    __shared__ float red[18];
    int warp = tid >> 5, lane = tid & 31;
    if (lane == 0) { red[warp*2] = s1; red[warp*2 + 1] = s2; }
    __syncthreads();
    if (tid == 0) {
        float t1 = 0.f, t2 = 0.f;
        #pragma unroll
        for (int w = 0; w < 8; w++) { t1 += red[w*2]; t2 += red[w*2 + 1]; }
        float mu = t1 * (1.f/DMODEL);
        float var = t2 * (1.f/DMODEL) - mu*mu;
        red[16] = mu;
        red[17] = rsqrtf(var + LN_EPS);
    }
    __syncthreads();
    float mu = red[16], inv = red[17];

    float4 g4 = *(const float4*)&gamma[tid*4];
    float4 b4 = *(const float4*)&beta[tid*4];
    float4 o;
    o.x = g4.x*(y[0] - mu)*inv + b4.x;
    o.y = g4.y*(y[1] - mu)*inv + b4.y;
    o.z = g4.z*(y[2] - mu)*inv + b4.z;
    o.w = g4.w*(y[3] - mu)*inv + b4.w;
    *(float4*)&out[(size_t)strm*ROWS*DMODEL + (size_t)row*DMODEL + tid*4] = o;
}

// ---------------- launch ----------------
extern "C" void kernel_launch(void* const* d_in, const int* in_sizes, int n_in,
                              void* d_out, int out_size) {
    const float* h     = (const float*)d_in[0];
    const float* g     = (const float*)d_in[1];
    const float* Wq    = (const float*)d_in[2];
    const float* Wk    = (const float*)d_in[3];
    const float* Wv    = (const float*)d_in[4];
    const float* Wo    = (const float*)d_in[5];
    const float* rwb   = (const float*)d_in[6];
    const float* gamma = (const float*)d_in[7];
    const float* beta  = (const float*)d_in[8];
    float* out = (float*)d_out;

    float *pAO;
    __nv_bfloat16 *pKVb, *pQb, *pAVb, *phgb, *pWqTb, *pWkvT, *pWob;
    cudaGetSymbolAddress((void**)&pKVb,  g_KVb);
    cudaGetSymbolAddress((void**)&pQb,   g_Qb);
    cudaGetSymbolAddress((void**)&pAO,   g_AO);
    cudaGetSymbolAddress((void**)&pAVb,  g_AVb);
    cudaGetSymbolAddress((void**)&phgb,  g_hgb);
    cudaGetSymbolAddress((void**)&pWqTb, g_WqTb);
    cudaGetSymbolAddress((void**)&pWkvT, g_WkvT);
    cudaGetSymbolAddress((void**)&pWob,  g_Wob);

    cudaFuncSetAttribute(bgemm, cudaFuncAttributeMaxDynamicSharedMemorySize, BSMEM);
    cudaFuncSetAttribute(flash_bf, cudaFuncAttributeMaxDynamicSharedMemorySize, FBSMEM);

    conv_hg<<<dim3(ROWS*DMODEL/1024, 2), 256>>>(h, g, phgb);
    conv_f2b<<<DMODEL*DMODEL/1024, 256>>>(Wo, pWob);
    transposeb3<<<dim3(32, 32, 3), dim3(32, 8)>>>(Wq, Wk, Wv, pWqTb, pWkvT);

    // (1) K+V projections: A = h, BT = [WkT;WvT], N=2048
    bgemm<<<dim3(16, 32), 256, BSMEM>>>(phgb, pWkvT, nullptr, pKVb, nullptr, 5);
    // (2) Q projections, both streams: A = [h;g] (M=8192), BT = WqT
    bgemm<<<dim3(8, 64), 256, BSMEM>>>(phgb, pWqTb, nullptr, pQb, rwb, 6);

    flash_bf<<<dim3(SEQ/128, BATCH*NHEAD, 2), 256, FBSMEM>>>(pQb, pKVb, pKVb + HEADSZ, pAVb);

    // (3) output projection, both streams: A = AV (M=8192), BT = Wo
    bgemm<<<dim3(8, 64), 256, BSMEM>>>(pAVb, pWob, pAO, nullptr, nullptr, 0);

    resid_ln<<<dim3(ROWS, 2), 256>>>(pAO, h, g, gamma, beta, out);
}